// round 8
// baseline (speedup 1.0000x reference)
#include <cuda_runtime.h>
#include <cuda_bf16.h>
#include <cstdint>

// ---------------------------------------------------------------------------
// Problem sizes (fixed)
// ---------------------------------------------------------------------------
#define BB 8
#define QQ 128
#define VV 512
#define HH 512

#define NQ (BB*QQ*HH)   // 524288
#define NV (BB*VV*HH)   // 2097152
#define NW (HH*HH)      // 262144

// ---------------------------------------------------------------------------
// Device scratch (no allocations allowed)
// ---------------------------------------------------------------------------
__device__ float g_qp[NQ];
__device__ float g_vp[NV];
__device__ __nv_bfloat16 g_qhi[NQ], g_qlo[NQ];
__device__ __nv_bfloat16 g_vhi[NV], g_vlo[NV];
__device__ __nv_bfloat16 g_wqhi[NW], g_wqlo[NW];
__device__ __nv_bfloat16 g_wvhi[NW], g_wvlo[NW];

// ---------------------------------------------------------------------------
// Fast transcendentals
// ---------------------------------------------------------------------------
__device__ __forceinline__ float fast_ex2(float x) {
    float y;
    asm("ex2.approx.ftz.f32 %0, %1;" : "=f"(y) : "f"(x));
    return y;
}
__device__ __forceinline__ float tanh_fast(float x) {
    float y;
    asm("tanh.approx.f32 %0, %1;" : "=f"(y) : "f"(x));
    return y;
}

// cp.async helpers
__device__ __forceinline__ void cp_async16(void* dst_smem, const void* src_gmem) {
    uint32_t d = (uint32_t)__cvta_generic_to_shared(dst_smem);
    asm volatile("cp.async.cg.shared.global [%0], [%1], 16;\n" :: "r"(d), "l"(src_gmem) : "memory");
}
__device__ __forceinline__ void cp_commit() {
    asm volatile("cp.async.commit_group;\n" ::: "memory");
}
__device__ __forceinline__ void cp_wait1() {
    asm volatile("cp.async.wait_group 1;\n" ::: "memory");
}
__device__ __forceinline__ void cp_wait0() {
    asm volatile("cp.async.wait_group 0;\n" ::: "memory");
}

// split a float4 into 4 hi bf16 (8B) and 4 lo bf16 (8B)
__device__ __forceinline__ void split4(float4 v, uint2* hi, uint2* lo) {
    __nv_bfloat16 h0 = __float2bfloat16(v.x);
    __nv_bfloat16 h1 = __float2bfloat16(v.y);
    __nv_bfloat16 h2 = __float2bfloat16(v.z);
    __nv_bfloat16 h3 = __float2bfloat16(v.w);
    __nv_bfloat16 l0 = __float2bfloat16(v.x - __bfloat162float(h0));
    __nv_bfloat16 l1 = __float2bfloat16(v.y - __bfloat162float(h1));
    __nv_bfloat16 l2 = __float2bfloat16(v.z - __bfloat162float(h2));
    __nv_bfloat16 l3 = __float2bfloat16(v.w - __bfloat162float(h3));
    __nv_bfloat162 hA = {h0, h1}, hB = {h2, h3};
    __nv_bfloat162 lA = {l0, l1}, lB = {l2, l3};
    hi->x = *(uint32_t*)&hA; hi->y = *(uint32_t*)&hB;
    lo->x = *(uint32_t*)&lA; lo->y = *(uint32_t*)&lB;
}

// ---------------------------------------------------------------------------
// K1: fused fp32 -> bf16 hi/lo split for query, values, Wq, Wv (float4 wide)
// ---------------------------------------------------------------------------
#define NQ4 (NQ/4)
#define NV4 (NV/4)
#define NW4 (NW/4)
#define NTOT4 (NQ4 + NV4 + 2*NW4)   // 851968

__global__ void convert_all_kernel(const float* __restrict__ query,
                                   const float* __restrict__ values,
                                   const float* __restrict__ Wq,
                                   const float* __restrict__ Wv) {
    int i = blockIdx.x * blockDim.x + threadIdx.x;
    const float* src;
    __nv_bfloat16 *hi, *lo;
    int j = i;
    if (j < NQ4)                    { src = query;  hi = g_qhi;  lo = g_qlo;  }
    else if ((j -= NQ4) < NV4)      { src = values; hi = g_vhi;  lo = g_vlo;  }
    else if ((j -= NV4) < NW4)      { src = Wq;     hi = g_wqhi; lo = g_wqlo; }
    else if ((j -= NW4) < NW4)      { src = Wv;     hi = g_wvhi; lo = g_wvlo; }
    else return;
    float4 x = ((const float4*)src)[j];
    uint2 h, l;
    split4(x, &h, &l);
    ((uint2*)hi)[j] = h;
    ((uint2*)lo)[j] = l;
}

// ---------------------------------------------------------------------------
// K2: merged projection GEMM on pre-split bf16, cp.async double-buffered.
// C[m][n] = sum_k A[m][k]*B[n][k] + bias[n]  (NT, 3-term split, fp32 acc)
// GBM=128, GBN=64, GBK=32, 256 threads, occ 3 -> 320 blocks in ONE wave.
// ---------------------------------------------------------------------------
#define GBM 128
#define GBN 64
#define CBK 32
#define CSTR (CBK + 8)            // 40 bf16 per row
#define OFF_AHI 0
#define OFF_ALO (GBM*CSTR)        // 5120
#define OFF_BHI (2*GBM*CSTR)      // 10240
#define OFF_BLO (2*GBM*CSTR + GBN*CSTR)  // 12800
#define BUFSZ (2*GBM*CSTR + 2*GBN*CSTR)  // 15360 bf16
#define GEMM_SMEM_BYTES (2*BUFSZ*2)      // 61440 B

#define QP_MTILES (BB*QQ/GBM)   // 8
#define VP_MTILES (BB*VV/GBM)   // 32
#define NKB (HH/CBK)            // 16

__device__ __forceinline__ void mma16816(float* d, const uint32_t* a, const uint32_t* b) {
    asm volatile(
        "mma.sync.aligned.m16n8k16.row.col.f32.bf16.bf16.f32 "
        "{%0,%1,%2,%3}, {%4,%5,%6,%7}, {%8,%9}, {%0,%1,%2,%3};"
        : "+f"(d[0]), "+f"(d[1]), "+f"(d[2]), "+f"(d[3])
        : "r"(a[0]), "r"(a[1]), "r"(a[2]), "r"(a[3]), "r"(b[0]), "r"(b[1]));
}

__global__ __launch_bounds__(256, 3) void gemm_both_kernel(
    const float* __restrict__ bq, const float* __restrict__ bv) {
    const int K = HH;
    const int N = HH;
    extern __shared__ __nv_bfloat16 gsm[];

    const __nv_bfloat16 *Ahi, *Alo, *Bhi, *Blo;
    const float* bias;
    float* C;
    int mt = blockIdx.x;
    if (mt < QP_MTILES) {
        Ahi = g_qhi; Alo = g_qlo; Bhi = g_wqhi; Blo = g_wqlo; bias = bq; C = g_qp;
    } else {
        mt -= QP_MTILES;
        Ahi = g_vhi; Alo = g_vlo; Bhi = g_wvhi; Blo = g_wvlo; bias = bv; C = g_vp;
    }
    const int m0 = mt * GBM;
    const int n0 = blockIdx.y * GBN;
    const int tid = threadIdx.x;
    const int wid = tid >> 5;
    const int lane = tid & 31;
    const int wm = (wid >> 1) * 32;
    const int wn = (wid & 1) * 32;
    const int gp = lane >> 2;
    const int tg = lane & 3;

    // cp.async coords: A tile 128x32 bf16 = 512 x16B chunks (2/thread);
    // B tile 64x32 = 256 chunks (1/thread)
    const int ra0 = tid >> 1;                 // wrong granularity? no:
    // linear chunk = j*256+tid; row = linear>>2 (4 chunks/row), col=(linear&3)*8
    const int ca = (tid & 3) * 8;
    const int rb = tid >> 2;

    float d[2][4][4];
#pragma unroll
    for (int mi = 0; mi < 2; mi++)
#pragma unroll
        for (int ni = 0; ni < 4; ni++)
#pragma unroll
            for (int r = 0; r < 4; r++) d[mi][ni][r] = 0.0f;

    // stage k-block kb into buffer dst
    auto load_kb = [&](__nv_bfloat16* dst, int k0) {
#pragma unroll
        for (int j = 0; j < 2; j++) {
            int r = (j * 256 + tid) >> 2;
            cp_async16(dst + OFF_AHI + r * CSTR + ca, Ahi + (size_t)(m0 + r) * K + k0 + ca);
        }
#pragma unroll
        for (int j = 0; j < 2; j++) {
            int r = (j * 256 + tid) >> 2;
            cp_async16(dst + OFF_ALO + r * CSTR + ca, Alo + (size_t)(m0 + r) * K + k0 + ca);
        }
        cp_async16(dst + OFF_BHI + rb * CSTR + ca, Bhi + (size_t)(n0 + rb) * K + k0 + ca);
        cp_async16(dst + OFF_BLO + rb * CSTR + ca, Blo + (size_t)(n0 + rb) * K + k0 + ca);
    };

    load_kb(gsm, 0);
    cp_commit();

    for (int kb = 0; kb < NKB; kb++) {
        if (kb + 1 < NKB) {
            load_kb(gsm + ((kb + 1) & 1) * BUFSZ, (kb + 1) * CBK);
            cp_commit();
            cp_wait1();
        } else {
            cp_wait0();
        }
        __syncthreads();

        const __nv_bfloat16* S = gsm + (kb & 1) * BUFSZ;
#pragma unroll
        for (int ks = 0; ks < CBK; ks += 16) {
            // hi*hi term
            uint32_t ah[2][4];
#pragma unroll
            for (int mi = 0; mi < 2; mi++) {
                int row = wm + mi * 16;
                ah[mi][0] = *(const uint32_t*)(S + OFF_AHI + (row + gp) * CSTR + ks + tg * 2);
                ah[mi][1] = *(const uint32_t*)(S + OFF_AHI + (row + gp + 8) * CSTR + ks + tg * 2);
                ah[mi][2] = *(const uint32_t*)(S + OFF_AHI + (row + gp) * CSTR + ks + tg * 2 + 8);
                ah[mi][3] = *(const uint32_t*)(S + OFF_AHI + (row + gp + 8) * CSTR + ks + tg * 2 + 8);
            }
            uint32_t bh[4][2];
#pragma unroll
            for (int ni = 0; ni < 4; ni++) {
                int col = wn + ni * 8;
                bh[ni][0] = *(const uint32_t*)(S + OFF_BHI + (col + gp) * CSTR + ks + tg * 2);
                bh[ni][1] = *(const uint32_t*)(S + OFF_BHI + (col + gp) * CSTR + ks + tg * 2 + 8);
            }
#pragma unroll
            for (int mi = 0; mi < 2; mi++)
#pragma unroll
                for (int ni = 0; ni < 4; ni++)
                    mma16816(d[mi][ni], ah[mi], bh[ni]);
            // hi*lo term
            {
                uint32_t bl[4][2];
#pragma unroll
                for (int ni = 0; ni < 4; ni++) {
                    int col = wn + ni * 8;
                    bl[ni][0] = *(const uint32_t*)(S + OFF_BLO + (col + gp) * CSTR + ks + tg * 2);
                    bl[ni][1] = *(const uint32_t*)(S + OFF_BLO + (col + gp) * CSTR + ks + tg * 2 + 8);
                }
#pragma unroll
                for (int mi = 0; mi < 2; mi++)
#pragma unroll
                    for (int ni = 0; ni < 4; ni++)
                        mma16816(d[mi][ni], ah[mi], bl[ni]);
            }
            // lo*hi term
            {
                uint32_t al[2][4];
#pragma unroll
                for (int mi = 0; mi < 2; mi++) {
                    int row = wm + mi * 16;
                    al[mi][0] = *(const uint32_t*)(S + OFF_ALO + (row + gp) * CSTR + ks + tg * 2);
                    al[mi][1] = *(const uint32_t*)(S + OFF_ALO + (row + gp + 8) * CSTR + ks + tg * 2);
                    al[mi][2] = *(const uint32_t*)(S + OFF_ALO + (row + gp) * CSTR + ks + tg * 2 + 8);
                    al[mi][3] = *(const uint32_t*)(S + OFF_ALO + (row + gp + 8) * CSTR + ks + tg * 2 + 8);
                }
#pragma unroll
                for (int mi = 0; mi < 2; mi++)
#pragma unroll
                    for (int ni = 0; ni < 4; ni++)
                        mma16816(d[mi][ni], al[mi], bh[ni]);
            }
        }
        __syncthreads();
    }

#pragma unroll
    for (int mi = 0; mi < 2; mi++)
#pragma unroll
        for (int ni = 0; ni < 4; ni++) {
            int r = m0 + wm + mi * 16 + gp;
            int c = n0 + wn + ni * 8 + tg * 2;
            float b0 = bias[c], b1 = bias[c + 1];
            float* Cp = C + (size_t)r * N + c;
            float2 v0 = make_float2(d[mi][ni][0] + b0, d[mi][ni][1] + b1);
            float2 v1 = make_float2(d[mi][ni][2] + b0, d[mi][ni][3] + b1);
            *(float2*)(Cp) = v0;
            *(float2*)(Cp + 8 * N) = v1;
        }
}

// ---------------------------------------------------------------------------
// K3: fused scores(tanh) + softmax + context (unchanged from Round 7)
// ---------------------------------------------------------------------------
#define QT 8
#define VT 32
#define NTILE (VV/VT)   // 16
#define HP (HH + 4)
#define VP (VV + 8)

#define SMEM_FLOATS (QT*HP + HH + QT*VP + 16 + VV + 2*VT*HP)
#define SMEM_BYTES (SMEM_FLOATS * 4)

__device__ __forceinline__ void load_tile_async(float* dst, const float* src, int tid) {
#pragma unroll
    for (int i = 0; i < (VT * 128) / 512; i++) {
        int linear = i * 512 + tid;
        int r = linear >> 7;
        int c = (linear & 127) << 2;
        cp_async16(dst + r * HP + c, src + r * HH + c);
    }
}

__global__ __launch_bounds__(512, 1) void attn_kernel(
    const float* __restrict__ qp, const float* __restrict__ vp,
    const float* __restrict__ values, const int* __restrict__ mask,
    const float* __restrict__ wc, const float* __restrict__ bc,
    float* __restrict__ out_ctx, float* __restrict__ out_w) {
    extern __shared__ float sm[];
    float* qp_s = sm;
    float* wc_s = qp_s + QT * HP;
    float* sc   = wc_s + HH;
    float* wsum = sc + QT * VP;
    int* mask_s = (int*)(wsum + 16);
    float* buf  = (float*)(mask_s + VV);

    const int tid = threadIdx.x;
    const int b = blockIdx.x >> 4;
    const int qt = blockIdx.x & 15;
    const int q0 = qt * QT;

    const float* vpb = vp + (size_t)b * VV * HH;
    const float* valb = values + (size_t)b * VV * HH;

    load_tile_async(buf, vpb, tid);
    cp_commit();

    for (int i = tid; i < QT * (HH / 4); i += 512) {
        int r = i / (HH / 4), c = i % (HH / 4);
        ((float4*)(qp_s + r * HP))[c] =
            ((const float4*)(qp + (size_t)(b * QQ + q0 + r) * HH))[c];
    }
    for (int i = tid; i < HH; i += 512) wc_s[i] = wc[i];
    for (int i = tid; i < VV; i += 512) mask_s[i] = mask[b * VV + i];
    const float bcv = bc[0];

    const int q = tid >> 6;
    const int vg = (tid >> 3) & 7;
    const int hc = tid & 7;

    for (int t = 0; t < NTILE; t++) {
        float* cur = buf + (t & 1) * VT * HP;
        if (t + 1 < NTILE) {
            load_tile_async(buf + ((t + 1) & 1) * VT * HP, vpb + (size_t)(t + 1) * VT * HH, tid);
            cp_commit();
            cp_wait1();
        } else {
            cp_wait0();
        }
        __syncthreads();

        const float* qrow = qp_s + q * HP;
        const float* wrow = wc_s;
        const float* v0p = cur + (vg * 4 + 0) * HP;
        const float* v1p = cur + (vg * 4 + 1) * HP;
        const float* v2p = cur + (vg * 4 + 2) * HP;
        const float* v3p = cur + (vg * 4 + 3) * HP;
        float acc0 = 0.f, acc1 = 0.f, acc2 = 0.f, acc3 = 0.f;
#pragma unroll
        for (int i = 0; i < 16; i++) {
            int h = i * 32 + hc * 4;
            float4 a = *(const float4*)(qrow + h);
            float4 w = *(const float4*)(wrow + h);
            float4 c0 = *(const float4*)(v0p + h);
            float4 c1 = *(const float4*)(v1p + h);
            float4 c2 = *(const float4*)(v2p + h);
            float4 c3 = *(const float4*)(v3p + h);
            acc0 = fmaf(w.x, tanh_fast(a.x + c0.x), acc0);
            acc0 = fmaf(w.y, tanh_fast(a.y + c0.y), acc0);
            acc0 = fmaf(w.z, tanh_fast(a.z + c0.z), acc0);
            acc0 = fmaf(w.w, tanh_fast(a.w + c0.w), acc0);
            acc1 = fmaf(w.x, tanh_fast(a.x + c1.x), acc1);
            acc1 = fmaf(w.y, tanh_fast(a.y + c1.y), acc1);
            acc1 = fmaf(w.z, tanh_fast(a.z + c1.z), acc1);
            acc1 = fmaf(w.w, tanh_fast(a.w + c1.w), acc1);
            acc2 = fmaf(w.x, tanh_fast(a.x + c2.x), acc2);
            acc2 = fmaf(w.y, tanh_fast(a.y + c2.y), acc2);
            acc2 = fmaf(w.z, tanh_fast(a.z + c2.z), acc2);
            acc2 = fmaf(w.w, tanh_fast(a.w + c2.w), acc2);
            acc3 = fmaf(w.x, tanh_fast(a.x + c3.x), acc3);
            acc3 = fmaf(w.y, tanh_fast(a.y + c3.y), acc3);
            acc3 = fmaf(w.z, tanh_fast(a.z + c3.z), acc3);
            acc3 = fmaf(w.w, tanh_fast(a.w + c3.w), acc3);
        }
        acc0 += __shfl_xor_sync(0xffffffffu, acc0, 1);
        acc0 += __shfl_xor_sync(0xffffffffu, acc0, 2);
        acc0 += __shfl_xor_sync(0xffffffffu, acc0, 4);
        acc1 += __shfl_xor_sync(0xffffffffu, acc1, 1);
        acc1 += __shfl_xor_sync(0xffffffffu, acc1, 2);
        acc1 += __shfl_xor_sync(0xffffffffu, acc1, 4);
        acc2 += __shfl_xor_sync(0xffffffffu, acc2, 1);
        acc2 += __shfl_xor_sync(0xffffffffu, acc2, 2);
        acc2 += __shfl_xor_sync(0xffffffffu, acc2, 4);
        acc3 += __shfl_xor_sync(0xffffffffu, acc3, 1);
        acc3 += __shfl_xor_sync(0xffffffffu, acc3, 2);
        acc3 += __shfl_xor_sync(0xffffffffu, acc3, 4);
        if (hc < 4) {
            float myacc = (hc == 0) ? acc0 : (hc == 1) ? acc1 : (hc == 2) ? acc2 : acc3;
            int v = t * VT + vg * 4 + hc;
            float p = mask_s[v] ? fast_ex2((myacc + bcv) * 1.4426950408889634f) : 0.0f;
            sc[q * VP + v] = p;
        }
        __syncthreads();
    }

    load_tile_async(buf, valb, tid);
    cp_commit();

    const int vl = tid & 63;
    {
        float s = 0.0f;
#pragma unroll
        for (int j = 0; j < 8; j++) s += sc[q * VP + vl + 64 * j];
#pragma unroll
        for (int off = 16; off; off >>= 1) s += __shfl_down_sync(0xffffffffu, s, off);
        if ((tid & 31) == 0) wsum[tid >> 5] = s;
    }
    __syncthreads();
    const float inv = 1.0f / (wsum[2 * q] + wsum[2 * q + 1]);

    {
        float* outw_row = out_w + (size_t)(b * QQ + q0 + q) * VV;
#pragma unroll
        for (int j = 0; j < 8; j++) {
            int v = vl + 64 * j;
            float w = sc[q * VP + v] * inv;
            sc[q * VP + v] = w;
            outw_row[v] = w;
        }
    }

    const int ccol = tid & 127;
    const int cqg  = (tid >> 7) & 1;
    const int cvh  = tid >> 8;
    float4 ca0 = make_float4(0.f,0.f,0.f,0.f);
    float4 ca1 = make_float4(0.f,0.f,0.f,0.f);
    float4 ca2 = make_float4(0.f,0.f,0.f,0.f);
    float4 ca3 = make_float4(0.f,0.f,0.f,0.f);

    for (int t = 0; t < NTILE; t++) {
        float* cur = buf + (t & 1) * VT * HP;
        if (t + 1 < NTILE) {
            load_tile_async(buf + ((t + 1) & 1) * VT * HP, valb + (size_t)(t + 1) * VT * HH, tid);
            cp_commit();
            cp_wait1();
        } else {
            cp_wait0();
        }
        __syncthreads();

        const float* wq0 = sc + (cqg * 4 + 0) * VP + t * VT + cvh * 16;
        const float* wq1 = sc + (cqg * 4 + 1) * VP + t * VT + cvh * 16;
        const float* wq2 = sc + (cqg * 4 + 2) * VP + t * VT + cvh * 16;
        const float* wq3 = sc + (cqg * 4 + 3) * VP + t * VT + cvh * 16;
        const float* cb = cur + cvh * 16 * HP;
#pragma unroll
        for (int v = 0; v < 16; v++) {
            float4 c = ((const float4*)(cb + v * HP))[ccol];
            float w0 = wq0[v], w1 = wq1[v], w2 = wq2[v], w3 = wq3[v];
            ca0.x = fmaf(w0, c.x, ca0.x); ca0.y = fmaf(w0, c.y, ca0.y);
            ca0.z = fmaf(w0, c.z, ca0.z); ca0.w = fmaf(w0, c.w, ca0.w);
            ca1.x = fmaf(w1, c.x, ca1.x); ca1.y = fmaf(w1, c.y, ca1.y);
            ca1.z = fmaf(w1, c.z, ca1.z); ca1.w = fmaf(w1, c.w, ca1.w);
            ca2.x = fmaf(w2, c.x, ca2.x); ca2.y = fmaf(w2, c.y, ca2.y);
            ca2.z = fmaf(w2, c.z, ca2.z); ca2.w = fmaf(w2, c.w, ca2.w);
            ca3.x = fmaf(w3, c.x, ca3.x); ca3.y = fmaf(w3, c.y, ca3.y);
            ca3.z = fmaf(w3, c.z, ca3.z); ca3.w = fmaf(w3, c.w, ca3.w);
        }
        __syncthreads();
    }

    float4* xb = (float4*)qp_s;
    const int xi = (cqg * 128 + ccol) * 4;
    if (cvh == 1) {
        xb[xi + 0] = ca0; xb[xi + 1] = ca1; xb[xi + 2] = ca2; xb[xi + 3] = ca3;
    }
    __syncthreads();
    if (cvh == 0) {
        float4 p0 = xb[xi + 0], p1 = xb[xi + 1], p2 = xb[xi + 2], p3 = xb[xi + 3];
        ca0.x += p0.x; ca0.y += p0.y; ca0.z += p0.z; ca0.w += p0.w;
        ca1.x += p1.x; ca1.y += p1.y; ca1.z += p1.z; ca1.w += p1.w;
        ca2.x += p2.x; ca2.y += p2.y; ca2.z += p2.z; ca2.w += p2.w;
        ca3.x += p3.x; ca3.y += p3.y; ca3.z += p3.z; ca3.w += p3.w;
        float* oc = out_ctx + (size_t)(b * QQ + q0 + cqg * 4) * HH;
        ((float4*)(oc + 0 * HH))[ccol] = ca0;
        ((float4*)(oc + 1 * HH))[ccol] = ca1;
        ((float4*)(oc + 2 * HH))[ccol] = ca2;
        ((float4*)(oc + 3 * HH))[ccol] = ca3;
    }
}

// ---------------------------------------------------------------------------
// Launch
// ---------------------------------------------------------------------------
extern "C" void kernel_launch(void* const* d_in, const int* in_sizes, int n_in,
                              void* d_out, int out_size) {
    const float* query  = (const float*)d_in[0];
    const float* values = (const float*)d_in[1];
    const int*   mask   = (const int*)d_in[2];
    const float* Wq     = (const float*)d_in[3];
    const float* bq     = (const float*)d_in[4];
    const float* Wv     = (const float*)d_in[5];
    const float* bv     = (const float*)d_in[6];
    const float* wc     = (const float*)d_in[7];
    const float* bc     = (const float*)d_in[8];

    float* out_ctx = (float*)d_out;
    float* out_w   = (float*)d_out + (size_t)BB * QQ * HH;

    void *qp, *vp;
    cudaGetSymbolAddress(&qp, g_qp);
    cudaGetSymbolAddress(&vp, g_vp);

    // K1: fp32 -> bf16 hi/lo split (float4-wide, one launch)
    convert_all_kernel<<<NTOT4 / 256, 256>>>(query, values, Wq, Wv);

    // K2: both projections in ONE launch, occ-3 pipelined bf16 GEMM
    cudaFuncSetAttribute(gemm_both_kernel, cudaFuncAttributeMaxDynamicSharedMemorySize, GEMM_SMEM_BYTES);
    dim3 gboth(QP_MTILES + VP_MTILES, HH / GBN);   // (40, 8)
    gemm_both_kernel<<<gboth, 256, GEMM_SMEM_BYTES>>>(bq, bv);

    // K3: fused tanh-scores + softmax + context (pipelined)
    cudaFuncSetAttribute(attn_kernel, cudaFuncAttributeMaxDynamicSharedMemorySize, SMEM_BYTES);
    attn_kernel<<<BB * (QQ / QT), 512, SMEM_BYTES>>>(
        (const float*)qp, (const float*)vp, values, mask, wc, bc, out_ctx, out_w);
}

// round 10
// speedup vs baseline: 1.1298x; 1.1298x over previous
#include <cuda_runtime.h>
#include <cuda_bf16.h>
#include <cstdint>

// ---------------------------------------------------------------------------
// Problem sizes (fixed)
// ---------------------------------------------------------------------------
#define BB 8
#define QQ 128
#define VV 512
#define HH 512

#define NQ (BB*QQ*HH)
#define NV (BB*VV*HH)

// ---------------------------------------------------------------------------
// Device scratch (no allocations allowed)
// ---------------------------------------------------------------------------
__device__ float g_qp[NQ];
__device__ float g_vp[NV];
__device__ float g_sc[BB*QQ*VV];   // exp-masked unnormalized scores (2 MB)

// ---------------------------------------------------------------------------
// Fast transcendentals
// ---------------------------------------------------------------------------
__device__ __forceinline__ float fast_ex2(float x) {
    float y;
    asm("ex2.approx.ftz.f32 %0, %1;" : "=f"(y) : "f"(x));
    return y;
}
__device__ __forceinline__ float tanh_fast(float x) {
    float y;
    asm("tanh.approx.f32 %0, %1;" : "=f"(y) : "f"(x));
    return y;
}

// cp.async helpers
__device__ __forceinline__ void cp_async16(void* dst_smem, const void* src_gmem) {
    uint32_t d = (uint32_t)__cvta_generic_to_shared(dst_smem);
    asm volatile("cp.async.cg.shared.global [%0], [%1], 16;\n" :: "r"(d), "l"(src_gmem) : "memory");
}
__device__ __forceinline__ void cp_commit() {
    asm volatile("cp.async.commit_group;\n" ::: "memory");
}
__device__ __forceinline__ void cp_wait1() {
    asm volatile("cp.async.wait_group 1;\n" ::: "memory");
}
__device__ __forceinline__ void cp_wait0() {
    asm volatile("cp.async.wait_group 0;\n" ::: "memory");
}

// ---------------------------------------------------------------------------
// K2: merged projection GEMM (qp + vp in one launch), GBK=64 — R7 version.
// C[m][n] = sum_k A[m][k]*B[n][k] + bias[n]  (NT, 3x bf16 split, fp32 acc)
// ---------------------------------------------------------------------------
#define GBM 128
#define GBN 64
#define GBK 64
#define GSTRIDE (GBK + 8)
#define QP_MTILES (BB*QQ/GBM)   // 8
#define VP_MTILES (BB*VV/GBM)   // 32

#define GEMM_SMEM_BF16 (2*GBM*GSTRIDE + 2*GBN*GSTRIDE)
#define GEMM_SMEM_BYTES (GEMM_SMEM_BF16 * 2)

__device__ __forceinline__ void mma16816(float* d, const uint32_t* a, const uint32_t* b) {
    asm volatile(
        "mma.sync.aligned.m16n8k16.row.col.f32.bf16.bf16.f32 "
        "{%0,%1,%2,%3}, {%4,%5,%6,%7}, {%8,%9}, {%0,%1,%2,%3};"
        : "+f"(d[0]), "+f"(d[1]), "+f"(d[2]), "+f"(d[3])
        : "r"(a[0]), "r"(a[1]), "r"(a[2]), "r"(a[3]), "r"(b[0]), "r"(b[1]));
}

__device__ __forceinline__ void split4(float4 v, uint2* hi, uint2* lo) {
    __nv_bfloat16 h0 = __float2bfloat16(v.x);
    __nv_bfloat16 h1 = __float2bfloat16(v.y);
    __nv_bfloat16 h2 = __float2bfloat16(v.z);
    __nv_bfloat16 h3 = __float2bfloat16(v.w);
    __nv_bfloat16 l0 = __float2bfloat16(v.x - __bfloat162float(h0));
    __nv_bfloat16 l1 = __float2bfloat16(v.y - __bfloat162float(h1));
    __nv_bfloat16 l2 = __float2bfloat16(v.z - __bfloat162float(h2));
    __nv_bfloat16 l3 = __float2bfloat16(v.w - __bfloat162float(h3));
    __nv_bfloat162 hA = {h0, h1}, hB = {h2, h3};
    __nv_bfloat162 lA = {l0, l1}, lB = {l2, l3};
    hi->x = *(uint32_t*)&hA; hi->y = *(uint32_t*)&hB;
    lo->x = *(uint32_t*)&lA; lo->y = *(uint32_t*)&lB;
}

__global__ __launch_bounds__(256, 2) void gemm_both_kernel(
    const float* __restrict__ query, const float* __restrict__ Wq,
    const float* __restrict__ bq,
    const float* __restrict__ values, const float* __restrict__ Wv,
    const float* __restrict__ bv) {
    const int K = HH;
    const int N = HH;
    extern __shared__ __nv_bfloat16 gsm[];
    __nv_bfloat16* As = gsm;
    __nv_bfloat16* Bs = gsm + 2 * GBM * GSTRIDE;

    const float *A, *B, *bias;
    float* C;
    int mt = blockIdx.x;
    if (mt < QP_MTILES) {
        A = query; B = Wq; bias = bq; C = g_qp;
    } else {
        mt -= QP_MTILES;
        A = values; B = Wv; bias = bv; C = g_vp;
    }
    const int m0 = mt * GBM;
    const int n0 = blockIdx.y * GBN;
    const int tid = threadIdx.x;
    const int wid = tid >> 5;
    const int lane = tid & 31;
    const int wm = (wid >> 1) * 32;
    const int wn = (wid & 1) * 32;
    const int gp = lane >> 2;
    const int tg = lane & 3;

    const int sr = tid >> 4;
    const int scc = (tid & 15) * 4;

    float d[2][4][4];
#pragma unroll
    for (int mi = 0; mi < 2; mi++)
#pragma unroll
        for (int ni = 0; ni < 4; ni++)
#pragma unroll
            for (int r = 0; r < 4; r++) d[mi][ni][r] = 0.0f;

    float4 aReg[8], bReg[4];
#pragma unroll
    for (int i = 0; i < 8; i++)
        aReg[i] = *(const float4*)(A + (size_t)(m0 + i * 16 + sr) * K + scc);
#pragma unroll
    for (int i = 0; i < 4; i++)
        bReg[i] = *(const float4*)(B + (size_t)(n0 + i * 16 + sr) * K + scc);

    for (int k0 = 0; k0 < K; k0 += GBK) {
#pragma unroll
        for (int i = 0; i < 8; i++) {
            uint2 hi, lo;
            split4(aReg[i], &hi, &lo);
            int r = i * 16 + sr;
            *(uint2*)(As + r * GSTRIDE + scc) = hi;
            *(uint2*)(As + GBM * GSTRIDE + r * GSTRIDE + scc) = lo;
        }
#pragma unroll
        for (int i = 0; i < 4; i++) {
            uint2 hi, lo;
            split4(bReg[i], &hi, &lo);
            int r = i * 16 + sr;
            *(uint2*)(Bs + r * GSTRIDE + scc) = hi;
            *(uint2*)(Bs + GBN * GSTRIDE + r * GSTRIDE + scc) = lo;
        }
        __syncthreads();

        if (k0 + GBK < K) {
            int kn = k0 + GBK;
#pragma unroll
            for (int i = 0; i < 8; i++)
                aReg[i] = *(const float4*)(A + (size_t)(m0 + i * 16 + sr) * K + kn + scc);
#pragma unroll
            for (int i = 0; i < 4; i++)
                bReg[i] = *(const float4*)(B + (size_t)(n0 + i * 16 + sr) * K + kn + scc);
        }

#pragma unroll
        for (int ks = 0; ks < GBK; ks += 16) {
            uint32_t a[2][2][4];
            uint32_t bf[2][4][2];
#pragma unroll
            for (int s = 0; s < 2; s++) {
                const __nv_bfloat16* Ab = As + s * GBM * GSTRIDE;
                const __nv_bfloat16* Bb = Bs + s * GBN * GSTRIDE;
#pragma unroll
                for (int mi = 0; mi < 2; mi++) {
                    int row = wm + mi * 16;
                    a[s][mi][0] = *(const uint32_t*)(Ab + (row + gp) * GSTRIDE + ks + tg * 2);
                    a[s][mi][1] = *(const uint32_t*)(Ab + (row + gp + 8) * GSTRIDE + ks + tg * 2);
                    a[s][mi][2] = *(const uint32_t*)(Ab + (row + gp) * GSTRIDE + ks + tg * 2 + 8);
                    a[s][mi][3] = *(const uint32_t*)(Ab + (row + gp + 8) * GSTRIDE + ks + tg * 2 + 8);
                }
#pragma unroll
                for (int ni = 0; ni < 4; ni++) {
                    int col = wn + ni * 8;
                    bf[s][ni][0] = *(const uint32_t*)(Bb + (col + gp) * GSTRIDE + ks + tg * 2);
                    bf[s][ni][1] = *(const uint32_t*)(Bb + (col + gp) * GSTRIDE + ks + tg * 2 + 8);
                }
            }
#pragma unroll
            for (int mi = 0; mi < 2; mi++)
#pragma unroll
                for (int ni = 0; ni < 4; ni++) {
                    mma16816(d[mi][ni], a[0][mi], bf[0][ni]);
                    mma16816(d[mi][ni], a[0][mi], bf[1][ni]);
                    mma16816(d[mi][ni], a[1][mi], bf[0][ni]);
                }
        }
        __syncthreads();
    }

#pragma unroll
    for (int mi = 0; mi < 2; mi++)
#pragma unroll
        for (int ni = 0; ni < 4; ni++) {
            int r = m0 + wm + mi * 16 + gp;
            int c = n0 + wn + ni * 8 + tg * 2;
            float b0 = bias[c], b1 = bias[c + 1];
            float* Cp = C + (size_t)r * N + c;
            float2 v0 = make_float2(d[mi][ni][0] + b0, d[mi][ni][1] + b1);
            float2 v1 = make_float2(d[mi][ni][2] + b0, d[mi][ni][3] + b1);
            *(float2*)(Cp) = v0;
            *(float2*)(Cp + 8 * N) = v1;
        }
}

// ---------------------------------------------------------------------------
// K3a: score kernel. grid = 8b x 16qt x 8vc = 1024 blocks, 256 threads, occ 2.
// Each block: 8 queries x 64 v-rows; exp-masked scores -> g_sc.
// Mapping: warp = one q; lane: hc = lane&7 (8 interleaved H chunks,
// h = i*32 + hc*4), vg = lane>>3 (4 groups of 4 rows). Per-LDS-phase the 8
// lanes read one row's 8 consecutive 16B slots -> conflict-free.
// ---------------------------------------------------------------------------
#define AVT 16
#define ANT 4            // 64 v per block = 4 tiles of 16
#define HP (HH + 4)      // 516
#define A_SMEM_FLOATS (8*HP + HH + 64 + 2*AVT*HP)
#define A_SMEM_BYTES (A_SMEM_FLOATS*4)   // ~84.9 KB

__device__ __forceinline__ void load_tile16(float* dst, const float* src, int tid) {
#pragma unroll
    for (int i = 0; i < 8; i++) {           // 16 rows x 128 chunks = 2048 / 256
        int lin = i * 256 + tid;
        int r = lin >> 7;
        int c = (lin & 127) << 2;
        cp_async16(dst + r * HP + c, src + (size_t)r * HH + c);
    }
}

__global__ __launch_bounds__(256, 2) void score_kernel(
    const float* __restrict__ qp, const float* __restrict__ vp,
    const int* __restrict__ mask, const float* __restrict__ wc,
    const float* __restrict__ bc) {
    extern __shared__ float sma[];
    float* qp_s = sma;                    // 8*HP
    float* wc_s = qp_s + 8 * HP;          // HH
    int* mask_s = (int*)(wc_s + HH);      // 64
    float* buf = (float*)(mask_s + 64);   // 2*AVT*HP

    const int tid = threadIdx.x;
    const int bx = blockIdx.x;
    const int vc = bx & 7;            // v chunk of 64
    const int qt = (bx >> 3) & 15;
    const int b = bx >> 7;
    const int q0 = qt * 8;
    const int v0 = vc * 64;

    const float* vpb = vp + (size_t)b * VV * HH + (size_t)v0 * HH;

    // prefetch v tile 0
    load_tile16(buf, vpb, tid);
    cp_commit();

    // qp tile (8x512), wc, mask chunk (plain loads; complete by first sync)
#pragma unroll
    for (int i = 0; i < 4; i++) {
        int lin = i * 256 + tid;
        int r = lin >> 7, c = lin & 127;
        ((float4*)(qp_s + r * HP))[c] =
            ((const float4*)(qp + (size_t)(b * QQ + q0 + r) * HH))[c];
    }
    if (tid < 128) ((float4*)wc_s)[tid] = ((const float4*)wc)[tid];
    if (tid < 64) mask_s[tid] = mask[b * VV + v0 + tid];
    const float bcv = bc[0];

    const int q = tid >> 5;
    const int lane = tid & 31;
    const int hc = lane & 7;
    const int vg = lane >> 3;      // 0..3

    for (int t = 0; t < ANT; t++) {
        float* cur = buf + (t & 1) * AVT * HP;
        if (t + 1 < ANT) {
            load_tile16(buf + ((t + 1) & 1) * AVT * HP, vpb + (size_t)(t + 1) * AVT * HH, tid);
            cp_commit();
            cp_wait1();
        } else {
            cp_wait0();
        }
        __syncthreads();

        const float* qrow = qp_s + q * HP;
        const float* wrow = wc_s;
        const float* v0p = cur + (vg * 4 + 0) * HP;
        const float* v1p = cur + (vg * 4 + 1) * HP;
        const float* v2p = cur + (vg * 4 + 2) * HP;
        const float* v3p = cur + (vg * 4 + 3) * HP;
        float acc0 = 0.f, acc1 = 0.f, acc2 = 0.f, acc3 = 0.f;
#pragma unroll
        for (int i = 0; i < 16; i++) {
            int h = i * 32 + hc * 4;
            float4 a = *(const float4*)(qrow + h);
            float4 w = *(const float4*)(wrow + h);
            float4 c0 = *(const float4*)(v0p + h);
            float4 c1 = *(const float4*)(v1p + h);
            float4 c2 = *(const float4*)(v2p + h);
            float4 c3 = *(const float4*)(v3p + h);
            acc0 = fmaf(w.x, tanh_fast(a.x + c0.x), acc0);
            acc0 = fmaf(w.y, tanh_fast(a.y + c0.y), acc0);
            acc0 = fmaf(w.z, tanh_fast(a.z + c0.z), acc0);
            acc0 = fmaf(w.w, tanh_fast(a.w + c0.w), acc0);
            acc1 = fmaf(w.x, tanh_fast(a.x + c1.x), acc1);
            acc1 = fmaf(w.y, tanh_fast(a.y + c1.y), acc1);
            acc1 = fmaf(w.z, tanh_fast(a.z + c1.z), acc1);
            acc1 = fmaf(w.w, tanh_fast(a.w + c1.w), acc1);
            acc2 = fmaf(w.x, tanh_fast(a.x + c2.x), acc2);
            acc2 = fmaf(w.y, tanh_fast(a.y + c2.y), acc2);
            acc2 = fmaf(w.z, tanh_fast(a.z + c2.z), acc2);
            acc2 = fmaf(w.w, tanh_fast(a.w + c2.w), acc2);
            acc3 = fmaf(w.x, tanh_fast(a.x + c3.x), acc3);
            acc3 = fmaf(w.y, tanh_fast(a.y + c3.y), acc3);
            acc3 = fmaf(w.z, tanh_fast(a.z + c3.z), acc3);
            acc3 = fmaf(w.w, tanh_fast(a.w + c3.w), acc3);
        }
        acc0 += __shfl_xor_sync(0xffffffffu, acc0, 1);
        acc0 += __shfl_xor_sync(0xffffffffu, acc0, 2);
        acc0 += __shfl_xor_sync(0xffffffffu, acc0, 4);
        acc1 += __shfl_xor_sync(0xffffffffu, acc1, 1);
        acc1 += __shfl_xor_sync(0xffffffffu, acc1, 2);
        acc1 += __shfl_xor_sync(0xffffffffu, acc1, 4);
        acc2 += __shfl_xor_sync(0xffffffffu, acc2, 1);
        acc2 += __shfl_xor_sync(0xffffffffu, acc2, 2);
        acc2 += __shfl_xor_sync(0xffffffffu, acc2, 4);
        acc3 += __shfl_xor_sync(0xffffffffu, acc3, 1);
        acc3 += __shfl_xor_sync(0xffffffffu, acc3, 2);
        acc3 += __shfl_xor_sync(0xffffffffu, acc3, 4);
        if (hc < 4) {
            float myacc = (hc == 0) ? acc0 : (hc == 1) ? acc1 : (hc == 2) ? acc2 : acc3;
            int vloc = t * AVT + vg * 4 + hc;
            float p = mask_s[vloc] ? fast_ex2((myacc + bcv) * 1.4426950408889634f) : 0.0f;
            g_sc[(size_t)(b * QQ + q0 + q) * VV + v0 + vloc] = p;
        }
        __syncthreads();
    }
}

// ---------------------------------------------------------------------------
// K3b: softmax + context. grid 128 = (b, qtile8), 512 threads.
// Reads g_sc; rowsum, normalize, write weights; v-split context (R7 scheme).
// ---------------------------------------------------------------------------
#define VT 32
#define NTILE (VV/VT)   // 16
#define VP (VV + 8)
#define B_SMEM_FLOATS (8*VP + 16 + 4096 + 2*VT*HP)
#define B_SMEM_BYTES (B_SMEM_FLOATS*4)   // ~165 KB

__device__ __forceinline__ void load_tile32(float* dst, const float* src, int tid) {
#pragma unroll
    for (int i = 0; i < 8; i++) {           // 32 rows x 128 chunks = 4096 / 512
        int lin = i * 512 + tid;
        int r = lin >> 7;
        int c = (lin & 127) << 2;
        cp_async16(dst + r * HP + c, src + (size_t)r * HH + c);
    }
}

__global__ __launch_bounds__(512, 1) void ctx_kernel(
    const float* __restrict__ values,
    float* __restrict__ out_ctx, float* __restrict__ out_w) {
    extern __shared__ float smb[];
    float* sc   = smb;               // 8*VP
    float* wsum = sc + 8 * VP;       // 16
    float* xb   = wsum + 16;         // 4096 (combine buffer)
    float* buf  = xb + 4096;         // 2*VT*HP

    const int tid = threadIdx.x;
    const int b = blockIdx.x >> 4;
    const int qt = blockIdx.x & 15;
    const int q0 = qt * 8;

    const float* valb = values + (size_t)b * VV * HH;

    // prefetch values tile 0
    load_tile32(buf, valb, tid);
    cp_commit();

    // load exp-scores into smem
#pragma unroll
    for (int i = 0; i < 2; i++) {
        int lin = i * 512 + tid;
        int r = lin >> 7, c = lin & 127;
        ((float4*)(sc + r * VP))[c] =
            ((const float4*)(g_sc + (size_t)(b * QQ + q0 + r) * VV))[c];
    }
    __syncthreads();

    // deterministic row sums
    const int q = tid >> 6;
    const int vl = tid & 63;
    {
        float s = 0.0f;
#pragma unroll
        for (int j = 0; j < 8; j++) s += sc[q * VP + vl + 64 * j];
#pragma unroll
        for (int off = 16; off; off >>= 1) s += __shfl_down_sync(0xffffffffu, s, off);
        if ((tid & 31) == 0) wsum[tid >> 5] = s;
    }
    __syncthreads();
    const float inv = 1.0f / (wsum[2 * q] + wsum[2 * q + 1]);

    // normalize + write weights
    {
        float* outw_row = out_w + (size_t)(b * QQ + q0 + q) * VV;
#pragma unroll
        for (int j = 0; j < 8; j++) {
            int v = vl + 64 * j;
            float w = sc[q * VP + v] * inv;
            sc[q * VP + v] = w;
            outw_row[v] = w;
        }
    }

    // context (v-split): thread = col(128) x qg(2) x vhalf(2)
    const int ccol = tid & 127;
    const int cqg  = (tid >> 7) & 1;
    const int cvh  = tid >> 8;
    float4 ca0 = make_float4(0.f,0.f,0.f,0.f);
    float4 ca1 = make_float4(0.f,0.f,0.f,0.f);
    float4 ca2 = make_float4(0.f,0.f,0.f,0.f);
    float4 ca3 = make_float4(0.f,0.f,0.f,0.f);

    for (int t = 0; t < NTILE; t++) {
        float* cur = buf + (t & 1) * VT * HP;
        if (t + 1 < NTILE) {
            load_tile32(buf + ((t + 1) & 1) * VT * HP, valb + (size_t)(t + 1) * VT * HH, tid);
            cp_commit();
            cp_wait1();
        } else {
            cp_wait0();
        }
        __syncthreads();

        const float* wq0 = sc + (cqg * 4 + 0) * VP + t * VT + cvh * 16;
        const float* wq1 = sc + (cqg * 4 + 1) * VP + t * VT + cvh * 16;
        const float* wq2 = sc + (cqg * 4 + 2) * VP + t * VT + cvh * 16;
        const float* wq3 = sc + (cqg * 4 + 3) * VP + t * VT + cvh * 16;
        const float* cb = cur + cvh * 16 * HP;
#pragma unroll
        for (int v = 0; v < 16; v++) {
            float4 c = ((const float4*)(cb + v * HP))[ccol];
            float w0 = wq0[v], w1 = wq1[v], w2 = wq2[v], w3 = wq3[v];
            ca0.x = fmaf(w0, c.x, ca0.x); ca0.y = fmaf(w0, c.y, ca0.y);
            ca0.z = fmaf(w0, c.z, ca0.z); ca0.w = fmaf(w0, c.w, ca0.w);
            ca1.x = fmaf(w1, c.x, ca1.x); ca1.y = fmaf(w1, c.y, ca1.y);
            ca1.z = fmaf(w1, c.z, ca1.z); ca1.w = fmaf(w1, c.w, ca1.w);
            ca2.x = fmaf(w2, c.x, ca2.x); ca2.y = fmaf(w2, c.y, ca2.y);
            ca2.z = fmaf(w2, c.z, ca2.z); ca2.w = fmaf(w2, c.w, ca2.w);
            ca3.x = fmaf(w3, c.x, ca3.x); ca3.y = fmaf(w3, c.y, ca3.y);
            ca3.z = fmaf(w3, c.z, ca3.z); ca3.w = fmaf(w3, c.w, ca3.w);
        }
        __syncthreads();
    }

    // combine v-halves (deterministic: vh0 + vh1) and write out
    float4* xbv = (float4*)xb;
    const int xi = (cqg * 128 + ccol) * 4;
    if (cvh == 1) {
        xbv[xi + 0] = ca0; xbv[xi + 1] = ca1; xbv[xi + 2] = ca2; xbv[xi + 3] = ca3;
    }
    __syncthreads();
    if (cvh == 0) {
        float4 p0 = xbv[xi + 0], p1 = xbv[xi + 1], p2 = xbv[xi + 2], p3 = xbv[xi + 3];
        ca0.x += p0.x; ca0.y += p0.y; ca0.z += p0.z; ca0.w += p0.w;
        ca1.x += p1.x; ca1.y += p1.y; ca1.z += p1.z; ca1.w += p1.w;
        ca2.x += p2.x; ca2.y += p2.y; ca2.z += p2.z; ca2.w += p2.w;
        ca3.x += p3.x; ca3.y += p3.y; ca3.z += p3.z; ca3.w += p3.w;
        float* oc = out_ctx + (size_t)(b * QQ + q0 + cqg * 4) * HH;
        ((float4*)(oc + 0 * HH))[ccol] = ca0;
        ((float4*)(oc + 1 * HH))[ccol] = ca1;
        ((float4*)(oc + 2 * HH))[ccol] = ca2;
        ((float4*)(oc + 3 * HH))[ccol] = ca3;
    }
}

// ---------------------------------------------------------------------------
// Launch
// ---------------------------------------------------------------------------
extern "C" void kernel_launch(void* const* d_in, const int* in_sizes, int n_in,
                              void* d_out, int out_size) {
    const float* query  = (const float*)d_in[0];
    const float* values = (const float*)d_in[1];
    const int*   mask   = (const int*)d_in[2];
    const float* Wq     = (const float*)d_in[3];
    const float* bq     = (const float*)d_in[4];
    const float* Wv     = (const float*)d_in[5];
    const float* bv     = (const float*)d_in[6];
    const float* wc     = (const float*)d_in[7];
    const float* bc     = (const float*)d_in[8];

    float* out_ctx = (float*)d_out;
    float* out_w   = (float*)d_out + (size_t)BB * QQ * HH;

    void *qp, *vp;
    cudaGetSymbolAddress(&qp, g_qp);
    cudaGetSymbolAddress(&vp, g_vp);

    // K2: both projections in ONE launch, GBK=64 (R7 version)
    cudaFuncSetAttribute(gemm_both_kernel, cudaFuncAttributeMaxDynamicSharedMemorySize, GEMM_SMEM_BYTES);
    dim3 gboth(QP_MTILES + VP_MTILES, HH / GBN);
    gemm_both_kernel<<<gboth, 256, GEMM_SMEM_BYTES>>>(query, Wq, bq, values, Wv, bv);

    // K3a: scores (1024 blocks, occ 2, chip-balanced MUFU)
    cudaFuncSetAttribute(score_kernel, cudaFuncAttributeMaxDynamicSharedMemorySize, A_SMEM_BYTES);
    score_kernel<<<1024, 256, A_SMEM_BYTES>>>(
        (const float*)qp, (const float*)vp, mask, wc, bc);

    // K3b: softmax + context
    cudaFuncSetAttribute(ctx_kernel, cudaFuncAttributeMaxDynamicSharedMemorySize, B_SMEM_BYTES);
    ctx_kernel<<<128, 512, B_SMEM_BYTES>>>(values, out_ctx, out_w);
}

// round 11
// speedup vs baseline: 1.1506x; 1.0184x over previous
#include <cuda_runtime.h>
#include <cuda_bf16.h>
#include <cstdint>

// ---------------------------------------------------------------------------
// Problem sizes (fixed)
// ---------------------------------------------------------------------------
#define BB 8
#define QQ 128
#define VV 512
#define HH 512

#define NQ (BB*QQ*HH)
#define NV (BB*VV*HH)

// ---------------------------------------------------------------------------
// Device scratch (no allocations allowed)
// ---------------------------------------------------------------------------
__device__ float g_qp[NQ];
__device__ float g_vp[NV];
__device__ float g_sc[BB*QQ*VV];   // exp-masked unnormalized scores (2 MB)

// ---------------------------------------------------------------------------
// Fast transcendentals
// ---------------------------------------------------------------------------
__device__ __forceinline__ float fast_ex2(float x) {
    float y;
    asm("ex2.approx.ftz.f32 %0, %1;" : "=f"(y) : "f"(x));
    return y;
}
__device__ __forceinline__ float tanh_fast(float x) {
    float y;
    asm("tanh.approx.f32 %0, %1;" : "=f"(y) : "f"(x));
    return y;
}

// cp.async helpers
__device__ __forceinline__ void cp_async16(void* dst_smem, const void* src_gmem) {
    uint32_t d = (uint32_t)__cvta_generic_to_shared(dst_smem);
    asm volatile("cp.async.cg.shared.global [%0], [%1], 16;\n" :: "r"(d), "l"(src_gmem) : "memory");
}
__device__ __forceinline__ void cp_commit() {
    asm volatile("cp.async.commit_group;\n" ::: "memory");
}
__device__ __forceinline__ void cp_wait1() {
    asm volatile("cp.async.wait_group 1;\n" ::: "memory");
}
__device__ __forceinline__ void cp_wait0() {
    asm volatile("cp.async.wait_group 0;\n" ::: "memory");
}

// ldmatrix x4 (b16, non-transposed)
__device__ __forceinline__ void ldsm_x4(uint32_t* r, uint32_t addr) {
    asm volatile("ldmatrix.sync.aligned.m8n8.x4.shared.b16 {%0,%1,%2,%3}, [%4];"
        : "=r"(r[0]), "=r"(r[1]), "=r"(r[2]), "=r"(r[3]) : "r"(addr));
}

// ---------------------------------------------------------------------------
// K2: merged projection GEMM (qp + vp in one launch), GBK=64, LDSM fragments.
// C[m][n] = sum_k A[m][k]*B[n][k] + bias[n]  (NT, 3x bf16 split, fp32 acc)
// ---------------------------------------------------------------------------
#define GBM 128
#define GBN 64
#define GBK 64
#define GSTRIDE (GBK + 8)
#define QP_MTILES (BB*QQ/GBM)   // 8
#define VP_MTILES (BB*VV/GBM)   // 32

#define GEMM_SMEM_BF16 (2*GBM*GSTRIDE + 2*GBN*GSTRIDE)
#define GEMM_SMEM_BYTES (GEMM_SMEM_BF16 * 2)
#define ALO_B (GBM*GSTRIDE*2)   // byte offset of A-lo plane
#define BLO_B (GBN*GSTRIDE*2)   // byte offset of B-lo plane (within Bs)

__device__ __forceinline__ void mma16816(float* d, const uint32_t* a, const uint32_t* b) {
    asm volatile(
        "mma.sync.aligned.m16n8k16.row.col.f32.bf16.bf16.f32 "
        "{%0,%1,%2,%3}, {%4,%5,%6,%7}, {%8,%9}, {%0,%1,%2,%3};"
        : "+f"(d[0]), "+f"(d[1]), "+f"(d[2]), "+f"(d[3])
        : "r"(a[0]), "r"(a[1]), "r"(a[2]), "r"(a[3]), "r"(b[0]), "r"(b[1]));
}

__device__ __forceinline__ void split4(float4 v, uint2* hi, uint2* lo) {
    __nv_bfloat16 h0 = __float2bfloat16(v.x);
    __nv_bfloat16 h1 = __float2bfloat16(v.y);
    __nv_bfloat16 h2 = __float2bfloat16(v.z);
    __nv_bfloat16 h3 = __float2bfloat16(v.w);
    __nv_bfloat16 l0 = __float2bfloat16(v.x - __bfloat162float(h0));
    __nv_bfloat16 l1 = __float2bfloat16(v.y - __bfloat162float(h1));
    __nv_bfloat16 l2 = __float2bfloat16(v.z - __bfloat162float(h2));
    __nv_bfloat16 l3 = __float2bfloat16(v.w - __bfloat162float(h3));
    __nv_bfloat162 hA = {h0, h1}, hB = {h2, h3};
    __nv_bfloat162 lA = {l0, l1}, lB = {l2, l3};
    hi->x = *(uint32_t*)&hA; hi->y = *(uint32_t*)&hB;
    lo->x = *(uint32_t*)&lA; lo->y = *(uint32_t*)&lB;
}

__global__ __launch_bounds__(256, 2) void gemm_both_kernel(
    const float* __restrict__ query, const float* __restrict__ Wq,
    const float* __restrict__ bq,
    const float* __restrict__ values, const float* __restrict__ Wv,
    const float* __restrict__ bv) {
    const int K = HH;
    const int N = HH;
    extern __shared__ __nv_bfloat16 gsm[];
    __nv_bfloat16* As = gsm;
    __nv_bfloat16* Bs = gsm + 2 * GBM * GSTRIDE;

    const float *A, *B, *bias;
    float* C;
    int mt = blockIdx.x;
    if (mt < QP_MTILES) {
        A = query; B = Wq; bias = bq; C = g_qp;
    } else {
        mt -= QP_MTILES;
        A = values; B = Wv; bias = bv; C = g_vp;
    }
    const int m0 = mt * GBM;
    const int n0 = blockIdx.y * GBN;
    const int tid = threadIdx.x;
    const int wid = tid >> 5;
    const int lane = tid & 31;
    const int wm = (wid >> 1) * 32;
    const int wn = (wid & 1) * 32;
    const int gp = lane >> 2;
    const int tg = lane & 3;

    const int sr = tid >> 4;
    const int scc = (tid & 15) * 4;

    // LDSM lane addresses (byte offsets within hi planes)
    const uint32_t As_b = (uint32_t)__cvta_generic_to_shared(As);
    const uint32_t Bs_b = (uint32_t)__cvta_generic_to_shared(Bs);
    const uint32_t aoff = ((wm + (lane & 15)) * GSTRIDE + ((lane >> 4) * 8)) * 2;
    const uint32_t boff = ((wn + ((lane >> 4) & 1) * 8 + (lane & 7)) * GSTRIDE
                           + ((lane >> 3) & 1) * 8) * 2;

    float d[2][4][4];
#pragma unroll
    for (int mi = 0; mi < 2; mi++)
#pragma unroll
        for (int ni = 0; ni < 4; ni++)
#pragma unroll
            for (int r = 0; r < 4; r++) d[mi][ni][r] = 0.0f;

    float4 aReg[8], bReg[4];
#pragma unroll
    for (int i = 0; i < 8; i++)
        aReg[i] = *(const float4*)(A + (size_t)(m0 + i * 16 + sr) * K + scc);
#pragma unroll
    for (int i = 0; i < 4; i++)
        bReg[i] = *(const float4*)(B + (size_t)(n0 + i * 16 + sr) * K + scc);

    for (int k0 = 0; k0 < K; k0 += GBK) {
#pragma unroll
        for (int i = 0; i < 8; i++) {
            uint2 hi, lo;
            split4(aReg[i], &hi, &lo);
            int r = i * 16 + sr;
            *(uint2*)(As + r * GSTRIDE + scc) = hi;
            *(uint2*)(As + GBM * GSTRIDE + r * GSTRIDE + scc) = lo;
        }
#pragma unroll
        for (int i = 0; i < 4; i++) {
            uint2 hi, lo;
            split4(bReg[i], &hi, &lo);
            int r = i * 16 + sr;
            *(uint2*)(Bs + r * GSTRIDE + scc) = hi;
            *(uint2*)(Bs + GBN * GSTRIDE + r * GSTRIDE + scc) = lo;
        }
        __syncthreads();

        if (k0 + GBK < K) {
            int kn = k0 + GBK;
#pragma unroll
            for (int i = 0; i < 8; i++)
                aReg[i] = *(const float4*)(A + (size_t)(m0 + i * 16 + sr) * K + kn + scc);
#pragma unroll
            for (int i = 0; i < 4; i++)
                bReg[i] = *(const float4*)(B + (size_t)(n0 + i * 16 + sr) * K + kn + scc);
        }

#pragma unroll
        for (int ks = 0; ks < GBK; ks += 16) {
            const uint32_t kb = ks * 2;   // byte advance along k
            uint32_t ah[2][4], al[2][4], bh[2][4], bl[2][4];
            ldsm_x4(ah[0], As_b + aoff + kb);
            ldsm_x4(ah[1], As_b + aoff + 16 * GSTRIDE * 2 + kb);
            ldsm_x4(al[0], As_b + ALO_B + aoff + kb);
            ldsm_x4(al[1], As_b + ALO_B + aoff + 16 * GSTRIDE * 2 + kb);
            ldsm_x4(bh[0], Bs_b + boff + kb);
            ldsm_x4(bh[1], Bs_b + boff + 16 * GSTRIDE * 2 + kb);
            ldsm_x4(bl[0], Bs_b + BLO_B + boff + kb);
            ldsm_x4(bl[1], Bs_b + BLO_B + boff + 16 * GSTRIDE * 2 + kb);
            // bX[p]: r0,r1 = ni=2p; r2,r3 = ni=2p+1
#pragma unroll
            for (int mi = 0; mi < 2; mi++)
#pragma unroll
                for (int ni = 0; ni < 4; ni++) {
                    const uint32_t* bhp = &bh[ni >> 1][(ni & 1) * 2];
                    const uint32_t* blp = &bl[ni >> 1][(ni & 1) * 2];
                    mma16816(d[mi][ni], ah[mi], bhp);   // hi*hi
                    mma16816(d[mi][ni], ah[mi], blp);   // hi*lo
                    mma16816(d[mi][ni], al[mi], bhp);   // lo*hi
                }
        }
        __syncthreads();
    }

#pragma unroll
    for (int mi = 0; mi < 2; mi++)
#pragma unroll
        for (int ni = 0; ni < 4; ni++) {
            int r = m0 + wm + mi * 16 + gp;
            int c = n0 + wn + ni * 8 + tg * 2;
            float b0 = bias[c], b1 = bias[c + 1];
            float* Cp = C + (size_t)r * N + c;
            float2 v0 = make_float2(d[mi][ni][0] + b0, d[mi][ni][1] + b1);
            float2 v1 = make_float2(d[mi][ni][2] + b0, d[mi][ni][3] + b1);
            *(float2*)(Cp) = v0;
            *(float2*)(Cp + 8 * N) = v1;
        }
}

// ---------------------------------------------------------------------------
// K3a: score kernel (unchanged from R10). 1024 blocks, 256 threads, occ 2.
// ---------------------------------------------------------------------------
#define AVT 16
#define ANT 4
#define HP (HH + 4)
#define A_SMEM_FLOATS (8*HP + HH + 64 + 2*AVT*HP)
#define A_SMEM_BYTES (A_SMEM_FLOATS*4)

__device__ __forceinline__ void load_tile16(float* dst, const float* src, int tid) {
#pragma unroll
    for (int i = 0; i < 8; i++) {
        int lin = i * 256 + tid;
        int r = lin >> 7;
        int c = (lin & 127) << 2;
        cp_async16(dst + r * HP + c, src + (size_t)r * HH + c);
    }
}

__global__ __launch_bounds__(256, 2) void score_kernel(
    const float* __restrict__ qp, const float* __restrict__ vp,
    const int* __restrict__ mask, const float* __restrict__ wc,
    const float* __restrict__ bc) {
    extern __shared__ float sma[];
    float* qp_s = sma;
    float* wc_s = qp_s + 8 * HP;
    int* mask_s = (int*)(wc_s + HH);
    float* buf = (float*)(mask_s + 64);

    const int tid = threadIdx.x;
    const int bx = blockIdx.x;
    const int vc = bx & 7;
    const int qt = (bx >> 3) & 15;
    const int b = bx >> 7;
    const int q0 = qt * 8;
    const int v0 = vc * 64;

    const float* vpb = vp + (size_t)b * VV * HH + (size_t)v0 * HH;

    load_tile16(buf, vpb, tid);
    cp_commit();

#pragma unroll
    for (int i = 0; i < 4; i++) {
        int lin = i * 256 + tid;
        int r = lin >> 7, c = lin & 127;
        ((float4*)(qp_s + r * HP))[c] =
            ((const float4*)(qp + (size_t)(b * QQ + q0 + r) * HH))[c];
    }
    if (tid < 128) ((float4*)wc_s)[tid] = ((const float4*)wc)[tid];
    if (tid < 64) mask_s[tid] = mask[b * VV + v0 + tid];
    const float bcv = bc[0];

    const int q = tid >> 5;
    const int lane = tid & 31;
    const int hc = lane & 7;
    const int vg = lane >> 3;

    for (int t = 0; t < ANT; t++) {
        float* cur = buf + (t & 1) * AVT * HP;
        if (t + 1 < ANT) {
            load_tile16(buf + ((t + 1) & 1) * AVT * HP, vpb + (size_t)(t + 1) * AVT * HH, tid);
            cp_commit();
            cp_wait1();
        } else {
            cp_wait0();
        }
        __syncthreads();

        const float* qrow = qp_s + q * HP;
        const float* wrow = wc_s;
        const float* v0p = cur + (vg * 4 + 0) * HP;
        const float* v1p = cur + (vg * 4 + 1) * HP;
        const float* v2p = cur + (vg * 4 + 2) * HP;
        const float* v3p = cur + (vg * 4 + 3) * HP;
        float acc0 = 0.f, acc1 = 0.f, acc2 = 0.f, acc3 = 0.f;
#pragma unroll
        for (int i = 0; i < 16; i++) {
            int h = i * 32 + hc * 4;
            float4 a = *(const float4*)(qrow + h);
            float4 w = *(const float4*)(wrow + h);
            float4 c0 = *(const float4*)(v0p + h);
            float4 c1 = *(const float4*)(v1p + h);
            float4 c2 = *(const float4*)(v2p + h);
            float4 c3 = *(const float4*)(v3p + h);
            acc0 = fmaf(w.x, tanh_fast(a.x + c0.x), acc0);
            acc0 = fmaf(w.y, tanh_fast(a.y + c0.y), acc0);
            acc0 = fmaf(w.z, tanh_fast(a.z + c0.z), acc0);
            acc0 = fmaf(w.w, tanh_fast(a.w + c0.w), acc0);
            acc1 = fmaf(w.x, tanh_fast(a.x + c1.x), acc1);
            acc1 = fmaf(w.y, tanh_fast(a.y + c1.y), acc1);
            acc1 = fmaf(w.z, tanh_fast(a.z + c1.z), acc1);
            acc1 = fmaf(w.w, tanh_fast(a.w + c1.w), acc1);
            acc2 = fmaf(w.x, tanh_fast(a.x + c2.x), acc2);
            acc2 = fmaf(w.y, tanh_fast(a.y + c2.y), acc2);
            acc2 = fmaf(w.z, tanh_fast(a.z + c2.z), acc2);
            acc2 = fmaf(w.w, tanh_fast(a.w + c2.w), acc2);
            acc3 = fmaf(w.x, tanh_fast(a.x + c3.x), acc3);
            acc3 = fmaf(w.y, tanh_fast(a.y + c3.y), acc3);
            acc3 = fmaf(w.z, tanh_fast(a.z + c3.z), acc3);
            acc3 = fmaf(w.w, tanh_fast(a.w + c3.w), acc3);
        }
        acc0 += __shfl_xor_sync(0xffffffffu, acc0, 1);
        acc0 += __shfl_xor_sync(0xffffffffu, acc0, 2);
        acc0 += __shfl_xor_sync(0xffffffffu, acc0, 4);
        acc1 += __shfl_xor_sync(0xffffffffu, acc1, 1);
        acc1 += __shfl_xor_sync(0xffffffffu, acc1, 2);
        acc1 += __shfl_xor_sync(0xffffffffu, acc1, 4);
        acc2 += __shfl_xor_sync(0xffffffffu, acc2, 1);
        acc2 += __shfl_xor_sync(0xffffffffu, acc2, 2);
        acc2 += __shfl_xor_sync(0xffffffffu, acc2, 4);
        acc3 += __shfl_xor_sync(0xffffffffu, acc3, 1);
        acc3 += __shfl_xor_sync(0xffffffffu, acc3, 2);
        acc3 += __shfl_xor_sync(0xffffffffu, acc3, 4);
        if (hc < 4) {
            float myacc = (hc == 0) ? acc0 : (hc == 1) ? acc1 : (hc == 2) ? acc2 : acc3;
            int vloc = t * AVT + vg * 4 + hc;
            float p = mask_s[vloc] ? fast_ex2((myacc + bcv) * 1.4426950408889634f) : 0.0f;
            g_sc[(size_t)(b * QQ + q0 + q) * VV + v0 + vloc] = p;
        }
        __syncthreads();
    }
}

// ---------------------------------------------------------------------------
// K3b: softmax + context (unchanged from R10). grid 128, 512 threads.
// ---------------------------------------------------------------------------
#define VT 32
#define NTILE (VV/VT)
#define VP (VV + 8)
#define B_SMEM_FLOATS (8*VP + 16 + 4096 + 2*VT*HP)
#define B_SMEM_BYTES (B_SMEM_FLOATS*4)

__device__ __forceinline__ void load_tile32(float* dst, const float* src, int tid) {
#pragma unroll
    for (int i = 0; i < 8; i++) {
        int lin = i * 512 + tid;
        int r = lin >> 7;
        int c = (lin & 127) << 2;
        cp_async16(dst + r * HP + c, src + (size_t)r * HH + c);
    }
}

__global__ __launch_bounds__(512, 1) void ctx_kernel(
    const float* __restrict__ values,
    float* __restrict__ out_ctx, float* __restrict__ out_w) {
    extern __shared__ float smb[];
    float* sc   = smb;
    float* wsum = sc + 8 * VP;
    float* xb   = wsum + 16;
    float* buf  = xb + 4096;

    const int tid = threadIdx.x;
    const int b = blockIdx.x >> 4;
    const int qt = blockIdx.x & 15;
    const int q0 = qt * 8;

    const float* valb = values + (size_t)b * VV * HH;

    load_tile32(buf, valb, tid);
    cp_commit();

#pragma unroll
    for (int i = 0; i < 2; i++) {
        int lin = i * 512 + tid;
        int r = lin >> 7, c = lin & 127;
        ((float4*)(sc + r * VP))[c] =
            ((const float4*)(g_sc + (size_t)(b * QQ + q0 + r) * VV))[c];
    }
    __syncthreads();

    const int q = tid >> 6;
    const int vl = tid & 63;
    {
        float s = 0.0f;
#pragma unroll
        for (int j = 0; j < 8; j++) s += sc[q * VP + vl + 64 * j];
#pragma unroll
        for (int off = 16; off; off >>= 1) s += __shfl_down_sync(0xffffffffu, s, off);
        if ((tid & 31) == 0) wsum[tid >> 5] = s;
    }
    __syncthreads();
    const float inv = 1.0f / (wsum[2 * q] + wsum[2 * q + 1]);

    {
        float* outw_row = out_w + (size_t)(b * QQ + q0 + q) * VV;
#pragma unroll
        for (int j = 0; j < 8; j++) {
            int v = vl + 64 * j;
            float w = sc[q * VP + v] * inv;
            sc[q * VP + v] = w;
            outw_row[v] = w;
        }
    }

    const int ccol = tid & 127;
    const int cqg  = (tid >> 7) & 1;
    const int cvh  = tid >> 8;
    float4 ca0 = make_float4(0.f,0.f,0.f,0.f);
    float4 ca1 = make_float4(0.f,0.f,0.f,0.f);
    float4 ca2 = make_float4(0.f,0.f,0.f,0.f);
    float4 ca3 = make_float4(0.f,0.f,0.f,0.f);

    for (int t = 0; t < NTILE; t++) {
        float* cur = buf + (t & 1) * VT * HP;
        if (t + 1 < NTILE) {
            load_tile32(buf + ((t + 1) & 1) * VT * HP, valb + (size_t)(t + 1) * VT * HH, tid);
            cp_commit();
            cp_wait1();
        } else {
            cp_wait0();
        }
        __syncthreads();

        const float* wq0 = sc + (cqg * 4 + 0) * VP + t * VT + cvh * 16;
        const float* wq1 = sc + (cqg * 4 + 1) * VP + t * VT + cvh * 16;
        const float* wq2 = sc + (cqg * 4 + 2) * VP + t * VT + cvh * 16;
        const float* wq3 = sc + (cqg * 4 + 3) * VP + t * VT + cvh * 16;
        const float* cb = cur + cvh * 16 * HP;
#pragma unroll
        for (int v = 0; v < 16; v++) {
            float4 c = ((const float4*)(cb + v * HP))[ccol];
            float w0 = wq0[v], w1 = wq1[v], w2 = wq2[v], w3 = wq3[v];
            ca0.x = fmaf(w0, c.x, ca0.x); ca0.y = fmaf(w0, c.y, ca0.y);
            ca0.z = fmaf(w0, c.z, ca0.z); ca0.w = fmaf(w0, c.w, ca0.w);
            ca1.x = fmaf(w1, c.x, ca1.x); ca1.y = fmaf(w1, c.y, ca1.y);
            ca1.z = fmaf(w1, c.z, ca1.z); ca1.w = fmaf(w1, c.w, ca1.w);
            ca2.x = fmaf(w2, c.x, ca2.x); ca2.y = fmaf(w2, c.y, ca2.y);
            ca2.z = fmaf(w2, c.z, ca2.z); ca2.w = fmaf(w2, c.w, ca2.w);
            ca3.x = fmaf(w3, c.x, ca3.x); ca3.y = fmaf(w3, c.y, ca3.y);
            ca3.z = fmaf(w3, c.z, ca3.z); ca3.w = fmaf(w3, c.w, ca3.w);
        }
        __syncthreads();
    }

    float4* xbv = (float4*)xb;
    const int xi = (cqg * 128 + ccol) * 4;
    if (cvh == 1) {
        xbv[xi + 0] = ca0; xbv[xi + 1] = ca1; xbv[xi + 2] = ca2; xbv[xi + 3] = ca3;
    }
    __syncthreads();
    if (cvh == 0) {
        float4 p0 = xbv[xi + 0], p1 = xbv[xi + 1], p2 = xbv[xi + 2], p3 = xbv[xi + 3];
        ca0.x += p0.x; ca0.y += p0.y; ca0.z += p0.z; ca0.w += p0.w;
        ca1.x += p1.x; ca1.y += p1.y; ca1.z += p1.z; ca1.w += p1.w;
        ca2.x += p2.x; ca2.y += p2.y; ca2.z += p2.z; ca2.w += p2.w;
        ca3.x += p3.x; ca3.y += p3.y; ca3.z += p3.z; ca3.w += p3.w;
        float* oc = out_ctx + (size_t)(b * QQ + q0 + cqg * 4) * HH;
        ((float4*)(oc + 0 * HH))[ccol] = ca0;
        ((float4*)(oc + 1 * HH))[ccol] = ca1;
        ((float4*)(oc + 2 * HH))[ccol] = ca2;
        ((float4*)(oc + 3 * HH))[ccol] = ca3;
    }
}

// ---------------------------------------------------------------------------
// Launch
// ---------------------------------------------------------------------------
extern "C" void kernel_launch(void* const* d_in, const int* in_sizes, int n_in,
                              void* d_out, int out_size) {
    const float* query  = (const float*)d_in[0];
    const float* values = (const float*)d_in[1];
    const int*   mask   = (const int*)d_in[2];
    const float* Wq     = (const float*)d_in[3];
    const float* bq     = (const float*)d_in[4];
    const float* Wv     = (const float*)d_in[5];
    const float* bv     = (const float*)d_in[6];
    const float* wc     = (const float*)d_in[7];
    const float* bc     = (const float*)d_in[8];

    float* out_ctx = (float*)d_out;
    float* out_w   = (float*)d_out + (size_t)BB * QQ * HH;

    void *qp, *vp;
    cudaGetSymbolAddress(&qp, g_qp);
    cudaGetSymbolAddress(&vp, g_vp);

    // K2: both projections in ONE launch, GBK=64, LDSM fragment loads
    cudaFuncSetAttribute(gemm_both_kernel, cudaFuncAttributeMaxDynamicSharedMemorySize, GEMM_SMEM_BYTES);
    dim3 gboth(QP_MTILES + VP_MTILES, HH / GBN);
    gemm_both_kernel<<<gboth, 256, GEMM_SMEM_BYTES>>>(query, Wq, bq, values, Wv, bv);

    // K3a: scores (1024 blocks, occ 2, chip-balanced MUFU)
    cudaFuncSetAttribute(score_kernel, cudaFuncAttributeMaxDynamicSharedMemorySize, A_SMEM_BYTES);
    score_kernel<<<1024, 256, A_SMEM_BYTES>>>(
        (const float*)qp, (const float*)vp, mask, wc, bc);

    // K3b: softmax + context
    cudaFuncSetAttribute(ctx_kernel, cudaFuncAttributeMaxDynamicSharedMemorySize, B_SMEM_BYTES);
    ctx_kernel<<<128, 512, B_SMEM_BYTES>>>(values, out_ctx, out_w);
}

// round 12
// speedup vs baseline: 1.1543x; 1.0033x over previous
#include <cuda_runtime.h>
#include <cuda_bf16.h>
#include <cstdint>

// ---------------------------------------------------------------------------
// Problem sizes (fixed)
// ---------------------------------------------------------------------------
#define BB 8
#define QQ 128
#define VV 512
#define HH 512

#define NQ (BB*QQ*HH)
#define NV (BB*VV*HH)

// ---------------------------------------------------------------------------
// Device scratch (no allocations allowed)
// ---------------------------------------------------------------------------
__device__ float g_qp[NQ];
__device__ float g_vp[NV];
__device__ float g_sc[BB*QQ*VV];   // exp-masked unnormalized scores (2 MB)

// ---------------------------------------------------------------------------
// Fast transcendentals
// ---------------------------------------------------------------------------
__device__ __forceinline__ float fast_ex2(float x) {
    float y;
    asm("ex2.approx.ftz.f32 %0, %1;" : "=f"(y) : "f"(x));
    return y;
}
__device__ __forceinline__ float tanh_fast(float x) {
    float y;
    asm("tanh.approx.f32 %0, %1;" : "=f"(y) : "f"(x));
    return y;
}

// cp.async helpers
__device__ __forceinline__ void cp_async16(void* dst_smem, const void* src_gmem) {
    uint32_t d = (uint32_t)__cvta_generic_to_shared(dst_smem);
    asm volatile("cp.async.cg.shared.global [%0], [%1], 16;\n" :: "r"(d), "l"(src_gmem) : "memory");
}
__device__ __forceinline__ void cp_commit() {
    asm volatile("cp.async.commit_group;\n" ::: "memory");
}
__device__ __forceinline__ void cp_wait1() {
    asm volatile("cp.async.wait_group 1;\n" ::: "memory");
}
__device__ __forceinline__ void cp_wait0() {
    asm volatile("cp.async.wait_group 0;\n" ::: "memory");
}

// ldmatrix x4 (b16, non-transposed)
__device__ __forceinline__ void ldsm_x4(uint32_t* r, uint32_t addr) {
    asm volatile("ldmatrix.sync.aligned.m8n8.x4.shared.b16 {%0,%1,%2,%3}, [%4];"
        : "=r"(r[0]), "=r"(r[1]), "=r"(r[2]), "=r"(r[3]) : "r"(addr));
}

// ---------------------------------------------------------------------------
// K2: merged projection GEMM (qp + vp), GBK=64, LDSM fragments, TERM-MAJOR
// MMA order (8 independent accumulators between reuses of the same one).
// C[m][n] = sum_k A[m][k]*B[n][k] + bias[n]  (NT, 3x bf16 split, fp32 acc)
// ---------------------------------------------------------------------------
#define GBM 128
#define GBN 64
#define GBK 64
#define GSTRIDE (GBK + 8)
#define QP_MTILES (BB*QQ/GBM)   // 8
#define VP_MTILES (BB*VV/GBM)   // 32

#define GEMM_SMEM_BF16 (2*GBM*GSTRIDE + 2*GBN*GSTRIDE)
#define GEMM_SMEM_BYTES (GEMM_SMEM_BF16 * 2)
#define ALO_B (GBM*GSTRIDE*2)   // byte offset of A-lo plane
#define BLO_B (GBN*GSTRIDE*2)   // byte offset of B-lo plane (within Bs)

__device__ __forceinline__ void mma16816(float* d, const uint32_t* a, const uint32_t* b) {
    asm volatile(
        "mma.sync.aligned.m16n8k16.row.col.f32.bf16.bf16.f32 "
        "{%0,%1,%2,%3}, {%4,%5,%6,%7}, {%8,%9}, {%0,%1,%2,%3};"
        : "+f"(d[0]), "+f"(d[1]), "+f"(d[2]), "+f"(d[3])
        : "r"(a[0]), "r"(a[1]), "r"(a[2]), "r"(a[3]), "r"(b[0]), "r"(b[1]));
}

__device__ __forceinline__ void split4(float4 v, uint2* hi, uint2* lo) {
    __nv_bfloat16 h0 = __float2bfloat16(v.x);
    __nv_bfloat16 h1 = __float2bfloat16(v.y);
    __nv_bfloat16 h2 = __float2bfloat16(v.z);
    __nv_bfloat16 h3 = __float2bfloat16(v.w);
    __nv_bfloat16 l0 = __float2bfloat16(v.x - __bfloat162float(h0));
    __nv_bfloat16 l1 = __float2bfloat16(v.y - __bfloat162float(h1));
    __nv_bfloat16 l2 = __float2bfloat16(v.z - __bfloat162float(h2));
    __nv_bfloat16 l3 = __float2bfloat16(v.w - __bfloat162float(h3));
    __nv_bfloat162 hA = {h0, h1}, hB = {h2, h3};
    __nv_bfloat162 lA = {l0, l1}, lB = {l2, l3};
    hi->x = *(uint32_t*)&hA; hi->y = *(uint32_t*)&hB;
    lo->x = *(uint32_t*)&lA; lo->y = *(uint32_t*)&lB;
}

__global__ __launch_bounds__(256, 2) void gemm_both_kernel(
    const float* __restrict__ query, const float* __restrict__ Wq,
    const float* __restrict__ bq,
    const float* __restrict__ values, const float* __restrict__ Wv,
    const float* __restrict__ bv) {
    const int K = HH;
    const int N = HH;
    extern __shared__ __nv_bfloat16 gsm[];
    __nv_bfloat16* As = gsm;
    __nv_bfloat16* Bs = gsm + 2 * GBM * GSTRIDE;

    const float *A, *B, *bias;
    float* C;
    int mt = blockIdx.x;
    if (mt < QP_MTILES) {
        A = query; B = Wq; bias = bq; C = g_qp;
    } else {
        mt -= QP_MTILES;
        A = values; B = Wv; bias = bv; C = g_vp;
    }
    const int m0 = mt * GBM;
    const int n0 = blockIdx.y * GBN;
    const int tid = threadIdx.x;
    const int wid = tid >> 5;
    const int lane = tid & 31;
    const int wm = (wid >> 1) * 32;
    const int wn = (wid & 1) * 32;
    const int gp = lane >> 2;
    const int tg = lane & 3;

    const int sr = tid >> 4;
    const int scc = (tid & 15) * 4;

    const uint32_t As_b = (uint32_t)__cvta_generic_to_shared(As);
    const uint32_t Bs_b = (uint32_t)__cvta_generic_to_shared(Bs);
    const uint32_t aoff = ((wm + (lane & 15)) * GSTRIDE + ((lane >> 4) * 8)) * 2;
    const uint32_t boff = ((wn + ((lane >> 4) & 1) * 8 + (lane & 7)) * GSTRIDE
                           + ((lane >> 3) & 1) * 8) * 2;

    float d[2][4][4];
#pragma unroll
    for (int mi = 0; mi < 2; mi++)
#pragma unroll
        for (int ni = 0; ni < 4; ni++)
#pragma unroll
            for (int r = 0; r < 4; r++) d[mi][ni][r] = 0.0f;

    float4 aReg[8], bReg[4];
#pragma unroll
    for (int i = 0; i < 8; i++)
        aReg[i] = *(const float4*)(A + (size_t)(m0 + i * 16 + sr) * K + scc);
#pragma unroll
    for (int i = 0; i < 4; i++)
        bReg[i] = *(const float4*)(B + (size_t)(n0 + i * 16 + sr) * K + scc);

    for (int k0 = 0; k0 < K; k0 += GBK) {
#pragma unroll
        for (int i = 0; i < 8; i++) {
            uint2 hi, lo;
            split4(aReg[i], &hi, &lo);
            int r = i * 16 + sr;
            *(uint2*)(As + r * GSTRIDE + scc) = hi;
            *(uint2*)(As + GBM * GSTRIDE + r * GSTRIDE + scc) = lo;
        }
#pragma unroll
        for (int i = 0; i < 4; i++) {
            uint2 hi, lo;
            split4(bReg[i], &hi, &lo);
            int r = i * 16 + sr;
            *(uint2*)(Bs + r * GSTRIDE + scc) = hi;
            *(uint2*)(Bs + GBN * GSTRIDE + r * GSTRIDE + scc) = lo;
        }
        __syncthreads();

        if (k0 + GBK < K) {
            int kn = k0 + GBK;
#pragma unroll
            for (int i = 0; i < 8; i++)
                aReg[i] = *(const float4*)(A + (size_t)(m0 + i * 16 + sr) * K + kn + scc);
#pragma unroll
            for (int i = 0; i < 4; i++)
                bReg[i] = *(const float4*)(B + (size_t)(n0 + i * 16 + sr) * K + kn + scc);
        }

#pragma unroll
        for (int ks = 0; ks < GBK; ks += 16) {
            const uint32_t kb = ks * 2;
            uint32_t ah[2][4], al[2][4], bh[2][4], bl[2][4];
            ldsm_x4(ah[0], As_b + aoff + kb);
            ldsm_x4(ah[1], As_b + aoff + 16 * GSTRIDE * 2 + kb);
            ldsm_x4(al[0], As_b + ALO_B + aoff + kb);
            ldsm_x4(al[1], As_b + ALO_B + aoff + 16 * GSTRIDE * 2 + kb);
            ldsm_x4(bh[0], Bs_b + boff + kb);
            ldsm_x4(bh[1], Bs_b + boff + 16 * GSTRIDE * 2 + kb);
            ldsm_x4(bl[0], Bs_b + BLO_B + boff + kb);
            ldsm_x4(bl[1], Bs_b + BLO_B + boff + 16 * GSTRIDE * 2 + kb);
            // TERM-MAJOR: 8 independent accumulators between reuses.
            // Per-accumulator order preserved: hh then hl then lh.
#pragma unroll
            for (int mi = 0; mi < 2; mi++)
#pragma unroll
                for (int ni = 0; ni < 4; ni++)
                    mma16816(d[mi][ni], ah[mi], &bh[ni >> 1][(ni & 1) * 2]);   // hi*hi
#pragma unroll
            for (int mi = 0; mi < 2; mi++)
#pragma unroll
                for (int ni = 0; ni < 4; ni++)
                    mma16816(d[mi][ni], ah[mi], &bl[ni >> 1][(ni & 1) * 2]);   // hi*lo
#pragma unroll
            for (int mi = 0; mi < 2; mi++)
#pragma unroll
                for (int ni = 0; ni < 4; ni++)
                    mma16816(d[mi][ni], al[mi], &bh[ni >> 1][(ni & 1) * 2]);   // lo*hi
        }
        __syncthreads();
    }

#pragma unroll
    for (int mi = 0; mi < 2; mi++)
#pragma unroll
        for (int ni = 0; ni < 4; ni++) {
            int r = m0 + wm + mi * 16 + gp;
            int c = n0 + wn + ni * 8 + tg * 2;
            float b0 = bias[c], b1 = bias[c + 1];
            float* Cp = C + (size_t)r * N + c;
            float2 v0 = make_float2(d[mi][ni][0] + b0, d[mi][ni][1] + b1);
            float2 v1 = make_float2(d[mi][ni][2] + b0, d[mi][ni][3] + b1);
            *(float2*)(Cp) = v0;
            *(float2*)(Cp + 8 * N) = v1;
        }
}

// ---------------------------------------------------------------------------
// K3a: score kernel (unchanged). 1024 blocks, 256 threads, occ 2.
// ---------------------------------------------------------------------------
#define AVT 16
#define ANT 4
#define HP (HH + 4)
#define A_SMEM_FLOATS (8*HP + HH + 64 + 2*AVT*HP)
#define A_SMEM_BYTES (A_SMEM_FLOATS*4)

__device__ __forceinline__ void load_tile16(float* dst, const float* src, int tid) {
#pragma unroll
    for (int i = 0; i < 8; i++) {
        int lin = i * 256 + tid;
        int r = lin >> 7;
        int c = (lin & 127) << 2;
        cp_async16(dst + r * HP + c, src + (size_t)r * HH + c);
    }
}

__global__ __launch_bounds__(256, 2) void score_kernel(
    const float* __restrict__ qp, const float* __restrict__ vp,
    const int* __restrict__ mask, const float* __restrict__ wc,
    const float* __restrict__ bc) {
    extern __shared__ float sma[];
    float* qp_s = sma;
    float* wc_s = qp_s + 8 * HP;
    int* mask_s = (int*)(wc_s + HH);
    float* buf = (float*)(mask_s + 64);

    const int tid = threadIdx.x;
    const int bx = blockIdx.x;
    const int vc = bx & 7;
    const int qt = (bx >> 3) & 15;
    const int b = bx >> 7;
    const int q0 = qt * 8;
    const int v0 = vc * 64;

    const float* vpb = vp + (size_t)b * VV * HH + (size_t)v0 * HH;

    load_tile16(buf, vpb, tid);
    cp_commit();

#pragma unroll
    for (int i = 0; i < 4; i++) {
        int lin = i * 256 + tid;
        int r = lin >> 7, c = lin & 127;
        ((float4*)(qp_s + r * HP))[c] =
            ((const float4*)(qp + (size_t)(b * QQ + q0 + r) * HH))[c];
    }
    if (tid < 128) ((float4*)wc_s)[tid] = ((const float4*)wc)[tid];
    if (tid < 64) mask_s[tid] = mask[b * VV + v0 + tid];
    const float bcv = bc[0];

    const int q = tid >> 5;
    const int lane = tid & 31;
    const int hc = lane & 7;
    const int vg = lane >> 3;

    for (int t = 0; t < ANT; t++) {
        float* cur = buf + (t & 1) * AVT * HP;
        if (t + 1 < ANT) {
            load_tile16(buf + ((t + 1) & 1) * AVT * HP, vpb + (size_t)(t + 1) * AVT * HH, tid);
            cp_commit();
            cp_wait1();
        } else {
            cp_wait0();
        }
        __syncthreads();

        const float* qrow = qp_s + q * HP;
        const float* wrow = wc_s;
        const float* v0p = cur + (vg * 4 + 0) * HP;
        const float* v1p = cur + (vg * 4 + 1) * HP;
        const float* v2p = cur + (vg * 4 + 2) * HP;
        const float* v3p = cur + (vg * 4 + 3) * HP;
        float acc0 = 0.f, acc1 = 0.f, acc2 = 0.f, acc3 = 0.f;
#pragma unroll
        for (int i = 0; i < 16; i++) {
            int h = i * 32 + hc * 4;
            float4 a = *(const float4*)(qrow + h);
            float4 w = *(const float4*)(wrow + h);
            float4 c0 = *(const float4*)(v0p + h);
            float4 c1 = *(const float4*)(v1p + h);
            float4 c2 = *(const float4*)(v2p + h);
            float4 c3 = *(const float4*)(v3p + h);
            acc0 = fmaf(w.x, tanh_fast(a.x + c0.x), acc0);
            acc0 = fmaf(w.y, tanh_fast(a.y + c0.y), acc0);
            acc0 = fmaf(w.z, tanh_fast(a.z + c0.z), acc0);
            acc0 = fmaf(w.w, tanh_fast(a.w + c0.w), acc0);
            acc1 = fmaf(w.x, tanh_fast(a.x + c1.x), acc1);
            acc1 = fmaf(w.y, tanh_fast(a.y + c1.y), acc1);
            acc1 = fmaf(w.z, tanh_fast(a.z + c1.z), acc1);
            acc1 = fmaf(w.w, tanh_fast(a.w + c1.w), acc1);
            acc2 = fmaf(w.x, tanh_fast(a.x + c2.x), acc2);
            acc2 = fmaf(w.y, tanh_fast(a.y + c2.y), acc2);
            acc2 = fmaf(w.z, tanh_fast(a.z + c2.z), acc2);
            acc2 = fmaf(w.w, tanh_fast(a.w + c2.w), acc2);
            acc3 = fmaf(w.x, tanh_fast(a.x + c3.x), acc3);
            acc3 = fmaf(w.y, tanh_fast(a.y + c3.y), acc3);
            acc3 = fmaf(w.z, tanh_fast(a.z + c3.z), acc3);
            acc3 = fmaf(w.w, tanh_fast(a.w + c3.w), acc3);
        }
        acc0 += __shfl_xor_sync(0xffffffffu, acc0, 1);
        acc0 += __shfl_xor_sync(0xffffffffu, acc0, 2);
        acc0 += __shfl_xor_sync(0xffffffffu, acc0, 4);
        acc1 += __shfl_xor_sync(0xffffffffu, acc1, 1);
        acc1 += __shfl_xor_sync(0xffffffffu, acc1, 2);
        acc1 += __shfl_xor_sync(0xffffffffu, acc1, 4);
        acc2 += __shfl_xor_sync(0xffffffffu, acc2, 1);
        acc2 += __shfl_xor_sync(0xffffffffu, acc2, 2);
        acc2 += __shfl_xor_sync(0xffffffffu, acc2, 4);
        acc3 += __shfl_xor_sync(0xffffffffu, acc3, 1);
        acc3 += __shfl_xor_sync(0xffffffffu, acc3, 2);
        acc3 += __shfl_xor_sync(0xffffffffu, acc3, 4);
        if (hc < 4) {
            float myacc = (hc == 0) ? acc0 : (hc == 1) ? acc1 : (hc == 2) ? acc2 : acc3;
            int vloc = t * AVT + vg * 4 + hc;
            float p = mask_s[vloc] ? fast_ex2((myacc + bcv) * 1.4426950408889634f) : 0.0f;
            g_sc[(size_t)(b * QQ + q0 + q) * VV + v0 + vloc] = p;
        }
        __syncthreads();
    }
}

// ---------------------------------------------------------------------------
// K3b: softmax + context (unchanged). grid 128, 512 threads.
// ---------------------------------------------------------------------------
#define VT 32
#define NTILE (VV/VT)
#define VP (VV + 8)
#define B_SMEM_FLOATS (8*VP + 16 + 4096 + 2*VT*HP)
#define B_SMEM_BYTES (B_SMEM_FLOATS*4)

__device__ __forceinline__ void load_tile32(float* dst, const float* src, int tid) {
#pragma unroll
    for (int i = 0; i < 8; i++) {
        int lin = i * 512 + tid;
        int r = lin >> 7;
        int c = (lin & 127) << 2;
        cp_async16(dst + r * HP + c, src + (size_t)r * HH + c);
    }
}

__global__ __launch_bounds__(512, 1) void ctx_kernel(
    const float* __restrict__ values,
    float* __restrict__ out_ctx, float* __restrict__ out_w) {
    extern __shared__ float smb[];
    float* sc   = smb;
    float* wsum = sc + 8 * VP;
    float* xb   = wsum + 16;
    float* buf  = xb + 4096;

    const int tid = threadIdx.x;
    const int b = blockIdx.x >> 4;
    const int qt = blockIdx.x & 15;
    const int q0 = qt * 8;

    const float* valb = values + (size_t)b * VV * HH;

    load_tile32(buf, valb, tid);
    cp_commit();

#pragma unroll
    for (int i = 0; i < 2; i++) {
        int lin = i * 512 + tid;
        int r = lin >> 7, c = lin & 127;
        ((float4*)(sc + r * VP))[c] =
            ((const float4*)(g_sc + (size_t)(b * QQ + q0 + r) * VV))[c];
    }
    __syncthreads();

    const int q = tid >> 6;
    const int vl = tid & 63;
    {
        float s = 0.0f;
#pragma unroll
        for (int j = 0; j < 8; j++) s += sc[q * VP + vl + 64 * j];
#pragma unroll
        for (int off = 16; off; off >>= 1) s += __shfl_down_sync(0xffffffffu, s, off);
        if ((tid & 31) == 0) wsum[tid >> 5] = s;
    }
    __syncthreads();
    const float inv = 1.0f / (wsum[2 * q] + wsum[2 * q + 1]);

    {
        float* outw_row = out_w + (size_t)(b * QQ + q0 + q) * VV;
#pragma unroll
        for (int j = 0; j < 8; j++) {
            int v = vl + 64 * j;
            float w = sc[q * VP + v] * inv;
            sc[q * VP + v] = w;
            outw_row[v] = w;
        }
    }

    const int ccol = tid & 127;
    const int cqg  = (tid >> 7) & 1;
    const int cvh  = tid >> 8;
    float4 ca0 = make_float4(0.f,0.f,0.f,0.f);
    float4 ca1 = make_float4(0.f,0.f,0.f,0.f);
    float4 ca2 = make_float4(0.f,0.f,0.f,0.f);
    float4 ca3 = make_float4(0.f,0.f,0.f,0.f);

    for (int t = 0; t < NTILE; t++) {
        float* cur = buf + (t & 1) * VT * HP;
        if (t + 1 < NTILE) {
            load_tile32(buf + ((t + 1) & 1) * VT * HP, valb + (size_t)(t + 1) * VT * HH, tid);
            cp_commit();
            cp_wait1();
        } else {
            cp_wait0();
        }
        __syncthreads();

        const float* wq0 = sc + (cqg * 4 + 0) * VP + t * VT + cvh * 16;
        const float* wq1 = sc + (cqg * 4 + 1) * VP + t * VT + cvh * 16;
        const float* wq2 = sc + (cqg * 4 + 2) * VP + t * VT + cvh * 16;
        const float* wq3 = sc + (cqg * 4 + 3) * VP + t * VT + cvh * 16;
        const float* cb = cur + cvh * 16 * HP;
#pragma unroll
        for (int v = 0; v < 16; v++) {
            float4 c = ((const float4*)(cb + v * HP))[ccol];
            float w0 = wq0[v], w1 = wq1[v], w2 = wq2[v], w3 = wq3[v];
            ca0.x = fmaf(w0, c.x, ca0.x); ca0.y = fmaf(w0, c.y, ca0.y);
            ca0.z = fmaf(w0, c.z, ca0.z); ca0.w = fmaf(w0, c.w, ca0.w);
            ca1.x = fmaf(w1, c.x, ca1.x); ca1.y = fmaf(w1, c.y, ca1.y);
            ca1.z = fmaf(w1, c.z, ca1.z); ca1.w = fmaf(w1, c.w, ca1.w);
            ca2.x = fmaf(w2, c.x, ca2.x); ca2.y = fmaf(w2, c.y, ca2.y);
            ca2.z = fmaf(w2, c.z, ca2.z); ca2.w = fmaf(w2, c.w, ca2.w);
            ca3.x = fmaf(w3, c.x, ca3.x); ca3.y = fmaf(w3, c.y, ca3.y);
            ca3.z = fmaf(w3, c.z, ca3.z); ca3.w = fmaf(w3, c.w, ca3.w);
        }
        __syncthreads();
    }

    float4* xbv = (float4*)xb;
    const int xi = (cqg * 128 + ccol) * 4;
    if (cvh == 1) {
        xbv[xi + 0] = ca0; xbv[xi + 1] = ca1; xbv[xi + 2] = ca2; xbv[xi + 3] = ca3;
    }
    __syncthreads();
    if (cvh == 0) {
        float4 p0 = xbv[xi + 0], p1 = xbv[xi + 1], p2 = xbv[xi + 2], p3 = xbv[xi + 3];
        ca0.x += p0.x; ca0.y += p0.y; ca0.z += p0.z; ca0.w += p0.w;
        ca1.x += p1.x; ca1.y += p1.y; ca1.z += p1.z; ca1.w += p1.w;
        ca2.x += p2.x; ca2.y += p2.y; ca2.z += p2.z; ca2.w += p2.w;
        ca3.x += p3.x; ca3.y += p3.y; ca3.z += p3.z; ca3.w += p3.w;
        float* oc = out_ctx + (size_t)(b * QQ + q0 + cqg * 4) * HH;
        ((float4*)(oc + 0 * HH))[ccol] = ca0;
        ((float4*)(oc + 1 * HH))[ccol] = ca1;
        ((float4*)(oc + 2 * HH))[ccol] = ca2;
        ((float4*)(oc + 3 * HH))[ccol] = ca3;
    }
}

// ---------------------------------------------------------------------------
// Launch
// ---------------------------------------------------------------------------
extern "C" void kernel_launch(void* const* d_in, const int* in_sizes, int n_in,
                              void* d_out, int out_size) {
    const float* query  = (const float*)d_in[0];
    const float* values = (const float*)d_in[1];
    const int*   mask   = (const int*)d_in[2];
    const float* Wq     = (const float*)d_in[3];
    const float* bq     = (const float*)d_in[4];
    const float* Wv     = (const float*)d_in[5];
    const float* bv     = (const float*)d_in[6];
    const float* wc     = (const float*)d_in[7];
    const float* bc     = (const float*)d_in[8];

    float* out_ctx = (float*)d_out;
    float* out_w   = (float*)d_out + (size_t)BB * QQ * HH;

    void *qp, *vp;
    cudaGetSymbolAddress(&qp, g_qp);
    cudaGetSymbolAddress(&vp, g_vp);

    // K2: both projections, term-major MMA ordering
    cudaFuncSetAttribute(gemm_both_kernel, cudaFuncAttributeMaxDynamicSharedMemorySize, GEMM_SMEM_BYTES);
    dim3 gboth(QP_MTILES + VP_MTILES, HH / GBN);
    gemm_both_kernel<<<gboth, 256, GEMM_SMEM_BYTES>>>(query, Wq, bq, values, Wv, bv);

    // K3a: scores (1024 blocks, occ 2, chip-balanced MUFU)
    cudaFuncSetAttribute(score_kernel, cudaFuncAttributeMaxDynamicSharedMemorySize, A_SMEM_BYTES);
    score_kernel<<<1024, 256, A_SMEM_BYTES>>>(
        (const float*)qp, (const float*)vp, mask, wc, bc);

    // K3b: softmax + context
    cudaFuncSetAttribute(ctx_kernel, cudaFuncAttributeMaxDynamicSharedMemorySize, B_SMEM_BYTES);
    ctx_kernel<<<128, 512, B_SMEM_BYTES>>>(values, out_ctx, out_w);
}

// round 13
// speedup vs baseline: 1.5061x; 1.3047x over previous
#include <cuda_runtime.h>
#include <cuda_bf16.h>
#include <cstdint>

#define BB 8
#define QQ 128
#define VV 512
#define HH 512

#define NQ (BB*QQ*HH)
#define NV (BB*VV*HH)

// ---------------------------------------------------------------------------
// Device scratch
// ---------------------------------------------------------------------------
__device__ float g_qp[NQ];
__device__ float g_vp[NV];
__device__ float g_sc[BB*QQ*VV];   // compact exp-scores
__device__ int   g_idx[BB*VV];     // compacted unmasked v indices (pad 0)
__device__ int   g_cnt[BB];

// ---------------------------------------------------------------------------
// Fast transcendentals
// ---------------------------------------------------------------------------
__device__ __forceinline__ float fast_ex2(float x) {
    float y;
    asm("ex2.approx.ftz.f32 %0, %1;" : "=f"(y) : "f"(x));
    return y;
}
__device__ __forceinline__ float tanh_fast(float x) {
    float y;
    asm("tanh.approx.f32 %0, %1;" : "=f"(y) : "f"(x));
    return y;
}

// cp.async helpers
__device__ __forceinline__ void cp_async16(void* dst_smem, const void* src_gmem) {
    uint32_t d = (uint32_t)__cvta_generic_to_shared(dst_smem);
    asm volatile("cp.async.cg.shared.global [%0], [%1], 16;\n" :: "r"(d), "l"(src_gmem) : "memory");
}
__device__ __forceinline__ void cp_commit() {
    asm volatile("cp.async.commit_group;\n" ::: "memory");
}
__device__ __forceinline__ void cp_wait1() {
    asm volatile("cp.async.wait_group 1;\n" ::: "memory");
}
__device__ __forceinline__ void cp_wait0() {
    asm volatile("cp.async.wait_group 0;\n" ::: "memory");
}

// ldmatrix x4 (b16)
__device__ __forceinline__ void ldsm_x4(uint32_t* r, uint32_t addr) {
    asm volatile("ldmatrix.sync.aligned.m8n8.x4.shared.b16 {%0,%1,%2,%3}, [%4];"
        : "=r"(r[0]), "=r"(r[1]), "=r"(r[2]), "=r"(r[3]) : "r"(addr));
}

// ---------------------------------------------------------------------------
// K0: mask compaction. 8 blocks (one per b), 512 threads. Deterministic.
// ---------------------------------------------------------------------------
__global__ void compact_kernel(const int* __restrict__ mask) {
    __shared__ int wsum_s[16];
    __shared__ int wbase_s[16];
    __shared__ int tot_s;
    const int b = blockIdx.x;
    const int tid = threadIdx.x;
    const int m = mask[b * VV + tid];
    unsigned bal = __ballot_sync(0xffffffffu, m != 0);
    int lanep = __popc(bal & ((1u << (tid & 31)) - 1u));
    int wid = tid >> 5;
    if ((tid & 31) == 0) wsum_s[wid] = __popc(bal);
    __syncthreads();
    if (tid == 0) {
        int acc = 0;
        for (int i = 0; i < 16; i++) { wbase_s[i] = acc; acc += wsum_s[i]; }
        tot_s = acc;
        g_cnt[b] = acc;
    }
    __syncthreads();
    if (m) g_idx[b * VV + wbase_s[wid] + lanep] = tid;     // [0, cnt)
    if (tid >= tot_s) g_idx[b * VV + tid] = 0;             // pad [cnt, 512)
}

// ---------------------------------------------------------------------------
// K2: merged projection GEMM (unchanged from R12 — at its HMMA floor)
// ---------------------------------------------------------------------------
#define GBM 128
#define GBN 64
#define GBK 64
#define GSTRIDE (GBK + 8)
#define QP_MTILES (BB*QQ/GBM)   // 8
#define VP_MTILES (BB*VV/GBM)   // 32

#define GEMM_SMEM_BF16 (2*GBM*GSTRIDE + 2*GBN*GSTRIDE)
#define GEMM_SMEM_BYTES (GEMM_SMEM_BF16 * 2)
#define ALO_B (GBM*GSTRIDE*2)
#define BLO_B (GBN*GSTRIDE*2)

__device__ __forceinline__ void mma16816(float* d, const uint32_t* a, const uint32_t* b) {
    asm volatile(
        "mma.sync.aligned.m16n8k16.row.col.f32.bf16.bf16.f32 "
        "{%0,%1,%2,%3}, {%4,%5,%6,%7}, {%8,%9}, {%0,%1,%2,%3};"
        : "+f"(d[0]), "+f"(d[1]), "+f"(d[2]), "+f"(d[3])
        : "r"(a[0]), "r"(a[1]), "r"(a[2]), "r"(a[3]), "r"(b[0]), "r"(b[1]));
}

__device__ __forceinline__ void split4(float4 v, uint2* hi, uint2* lo) {
    __nv_bfloat16 h0 = __float2bfloat16(v.x);
    __nv_bfloat16 h1 = __float2bfloat16(v.y);
    __nv_bfloat16 h2 = __float2bfloat16(v.z);
    __nv_bfloat16 h3 = __float2bfloat16(v.w);
    __nv_bfloat16 l0 = __float2bfloat16(v.x - __bfloat162float(h0));
    __nv_bfloat16 l1 = __float2bfloat16(v.y - __bfloat162float(h1));
    __nv_bfloat16 l2 = __float2bfloat16(v.z - __bfloat162float(h2));
    __nv_bfloat16 l3 = __float2bfloat16(v.w - __bfloat162float(h3));
    __nv_bfloat162 hA = {h0, h1}, hB = {h2, h3};
    __nv_bfloat162 lA = {l0, l1}, lB = {l2, l3};
    hi->x = *(uint32_t*)&hA; hi->y = *(uint32_t*)&hB;
    lo->x = *(uint32_t*)&lA; lo->y = *(uint32_t*)&lB;
}

__global__ __launch_bounds__(256, 2) void gemm_both_kernel(
    const float* __restrict__ query, const float* __restrict__ Wq,
    const float* __restrict__ bq,
    const float* __restrict__ values, const float* __restrict__ Wv,
    const float* __restrict__ bv) {
    const int K = HH;
    const int N = HH;
    extern __shared__ __nv_bfloat16 gsm[];
    __nv_bfloat16* As = gsm;
    __nv_bfloat16* Bs = gsm + 2 * GBM * GSTRIDE;

    const float *A, *B, *bias;
    float* C;
    int mt = blockIdx.x;
    if (mt < QP_MTILES) {
        A = query; B = Wq; bias = bq; C = g_qp;
    } else {
        mt -= QP_MTILES;
        A = values; B = Wv; bias = bv; C = g_vp;
    }
    const int m0 = mt * GBM;
    const int n0 = blockIdx.y * GBN;
    const int tid = threadIdx.x;
    const int wid = tid >> 5;
    const int lane = tid & 31;
    const int wm = (wid >> 1) * 32;
    const int wn = (wid & 1) * 32;
    const int gp = lane >> 2;
    const int tg = lane & 3;

    const int sr = tid >> 4;
    const int scc = (tid & 15) * 4;

    const uint32_t As_b = (uint32_t)__cvta_generic_to_shared(As);
    const uint32_t Bs_b = (uint32_t)__cvta_generic_to_shared(Bs);
    const uint32_t aoff = ((wm + (lane & 15)) * GSTRIDE + ((lane >> 4) * 8)) * 2;
    const uint32_t boff = ((wn + ((lane >> 4) & 1) * 8 + (lane & 7)) * GSTRIDE
                           + ((lane >> 3) & 1) * 8) * 2;

    float d[2][4][4];
#pragma unroll
    for (int mi = 0; mi < 2; mi++)
#pragma unroll
        for (int ni = 0; ni < 4; ni++)
#pragma unroll
            for (int r = 0; r < 4; r++) d[mi][ni][r] = 0.0f;

    float4 aReg[8], bReg[4];
#pragma unroll
    for (int i = 0; i < 8; i++)
        aReg[i] = *(const float4*)(A + (size_t)(m0 + i * 16 + sr) * K + scc);
#pragma unroll
    for (int i = 0; i < 4; i++)
        bReg[i] = *(const float4*)(B + (size_t)(n0 + i * 16 + sr) * K + scc);

    for (int k0 = 0; k0 < K; k0 += GBK) {
#pragma unroll
        for (int i = 0; i < 8; i++) {
            uint2 hi, lo;
            split4(aReg[i], &hi, &lo);
            int r = i * 16 + sr;
            *(uint2*)(As + r * GSTRIDE + scc) = hi;
            *(uint2*)(As + GBM * GSTRIDE + r * GSTRIDE + scc) = lo;
        }
#pragma unroll
        for (int i = 0; i < 4; i++) {
            uint2 hi, lo;
            split4(bReg[i], &hi, &lo);
            int r = i * 16 + sr;
            *(uint2*)(Bs + r * GSTRIDE + scc) = hi;
            *(uint2*)(Bs + GBN * GSTRIDE + r * GSTRIDE + scc) = lo;
        }
        __syncthreads();

        if (k0 + GBK < K) {
            int kn = k0 + GBK;
#pragma unroll
            for (int i = 0; i < 8; i++)
                aReg[i] = *(const float4*)(A + (size_t)(m0 + i * 16 + sr) * K + kn + scc);
#pragma unroll
            for (int i = 0; i < 4; i++)
                bReg[i] = *(const float4*)(B + (size_t)(n0 + i * 16 + sr) * K + kn + scc);
        }

#pragma unroll
        for (int ks = 0; ks < GBK; ks += 16) {
            const uint32_t kb = ks * 2;
            uint32_t ah[2][4], al[2][4], bh[2][4], bl[2][4];
            ldsm_x4(ah[0], As_b + aoff + kb);
            ldsm_x4(ah[1], As_b + aoff + 16 * GSTRIDE * 2 + kb);
            ldsm_x4(al[0], As_b + ALO_B + aoff + kb);
            ldsm_x4(al[1], As_b + ALO_B + aoff + 16 * GSTRIDE * 2 + kb);
            ldsm_x4(bh[0], Bs_b + boff + kb);
            ldsm_x4(bh[1], Bs_b + boff + 16 * GSTRIDE * 2 + kb);
            ldsm_x4(bl[0], Bs_b + BLO_B + boff + kb);
            ldsm_x4(bl[1], Bs_b + BLO_B + boff + 16 * GSTRIDE * 2 + kb);
#pragma unroll
            for (int mi = 0; mi < 2; mi++)
#pragma unroll
                for (int ni = 0; ni < 4; ni++)
                    mma16816(d[mi][ni], ah[mi], &bh[ni >> 1][(ni & 1) * 2]);
#pragma unroll
            for (int mi = 0; mi < 2; mi++)
#pragma unroll
                for (int ni = 0; ni < 4; ni++)
                    mma16816(d[mi][ni], ah[mi], &bl[ni >> 1][(ni & 1) * 2]);
#pragma unroll
            for (int mi = 0; mi < 2; mi++)
#pragma unroll
                for (int ni = 0; ni < 4; ni++)
                    mma16816(d[mi][ni], al[mi], &bh[ni >> 1][(ni & 1) * 2]);
        }
        __syncthreads();
    }

#pragma unroll
    for (int mi = 0; mi < 2; mi++)
#pragma unroll
        for (int ni = 0; ni < 4; ni++) {
            int r = m0 + wm + mi * 16 + gp;
            int c = n0 + wn + ni * 8 + tg * 2;
            float b0 = bias[c], b1 = bias[c + 1];
            float* Cp = C + (size_t)r * N + c;
            float2 v0 = make_float2(d[mi][ni][0] + b0, d[mi][ni][1] + b1);
            float2 v1 = make_float2(d[mi][ni][2] + b0, d[mi][ni][3] + b1);
            *(float2*)(Cp) = v0;
            *(float2*)(Cp + 8 * N) = v1;
        }
}

// ---------------------------------------------------------------------------
// K3a: score kernel over COMPACTED v slots. 1024 blocks (early-exit beyond
// cnt), 256 threads, occ 2. Gathered vp rows via idx list.
// ---------------------------------------------------------------------------
#define AVT 16
#define ANT 4
#define HP (HH + 4)
#define A_SMEM_FLOATS (8*HP + HH + 64 + 2*AVT*HP)
#define A_SMEM_BYTES (A_SMEM_FLOATS*4)

__device__ __forceinline__ void load_tile16_g(float* dst, const float* base,
                                              const int* idx, int tid) {
#pragma unroll
    for (int i = 0; i < 8; i++) {
        int lin = i * 256 + tid;
        int r = lin >> 7;
        int c = (lin & 127) << 2;
        cp_async16(dst + r * HP + c, base + (size_t)idx[r] * HH + c);
    }
}

__global__ __launch_bounds__(256, 2) void score_kernel(
    const float* __restrict__ qp, const float* __restrict__ vp,
    const float* __restrict__ wc, const float* __restrict__ bc) {
    extern __shared__ float sma[];
    float* qp_s = sma;                 // 8*HP
    float* wc_s = qp_s + 8 * HP;       // HH
    int* idx_s = (int*)(wc_s + HH);    // 64
    float* buf = (float*)(idx_s + 64); // 2*AVT*HP

    const int tid = threadIdx.x;
    const int bx = blockIdx.x;
    const int vc = bx & 7;
    const int qt = (bx >> 3) & 15;
    const int b = bx >> 7;
    const int q0 = qt * 8;
    const int v0 = vc * 64;

    const int cnt = g_cnt[b];
    if (v0 >= cnt) return;

    if (tid < 64) idx_s[tid] = g_idx[b * VV + v0 + tid];   // pad idx = 0 beyond cnt
    __syncthreads();

    const float* vpb = vp + (size_t)b * VV * HH;

    load_tile16_g(buf, vpb, idx_s, tid);
    cp_commit();

#pragma unroll
    for (int i = 0; i < 4; i++) {
        int lin = i * 256 + tid;
        int r = lin >> 7, c = lin & 127;
        ((float4*)(qp_s + r * HP))[c] =
            ((const float4*)(qp + (size_t)(b * QQ + q0 + r) * HH))[c];
    }
    if (tid < 128) ((float4*)wc_s)[tid] = ((const float4*)wc)[tid];
    const float bcv = bc[0];

    const int q = tid >> 5;
    const int lane = tid & 31;
    const int hc = lane & 7;
    const int vg = lane >> 3;

    for (int t = 0; t < ANT; t++) {
        float* cur = buf + (t & 1) * AVT * HP;
        if (t + 1 < ANT) {
            load_tile16_g(buf + ((t + 1) & 1) * AVT * HP, vpb, idx_s + (t + 1) * AVT, tid);
            cp_commit();
            cp_wait1();
        } else {
            cp_wait0();
        }
        __syncthreads();

        const float* qrow = qp_s + q * HP;
        const float* wrow = wc_s;
        const float* v0p = cur + (vg * 4 + 0) * HP;
        const float* v1p = cur + (vg * 4 + 1) * HP;
        const float* v2p = cur + (vg * 4 + 2) * HP;
        const float* v3p = cur + (vg * 4 + 3) * HP;
        float acc0 = 0.f, acc1 = 0.f, acc2 = 0.f, acc3 = 0.f;
#pragma unroll
        for (int i = 0; i < 16; i++) {
            int h = i * 32 + hc * 4;
            float4 a = *(const float4*)(qrow + h);
            float4 w = *(const float4*)(wrow + h);
            float4 c0 = *(const float4*)(v0p + h);
            float4 c1 = *(const float4*)(v1p + h);
            float4 c2 = *(const float4*)(v2p + h);
            float4 c3 = *(const float4*)(v3p + h);
            acc0 = fmaf(w.x, tanh_fast(a.x + c0.x), acc0);
            acc0 = fmaf(w.y, tanh_fast(a.y + c0.y), acc0);
            acc0 = fmaf(w.z, tanh_fast(a.z + c0.z), acc0);
            acc0 = fmaf(w.w, tanh_fast(a.w + c0.w), acc0);
            acc1 = fmaf(w.x, tanh_fast(a.x + c1.x), acc1);
            acc1 = fmaf(w.y, tanh_fast(a.y + c1.y), acc1);
            acc1 = fmaf(w.z, tanh_fast(a.z + c1.z), acc1);
            acc1 = fmaf(w.w, tanh_fast(a.w + c1.w), acc1);
            acc2 = fmaf(w.x, tanh_fast(a.x + c2.x), acc2);
            acc2 = fmaf(w.y, tanh_fast(a.y + c2.y), acc2);
            acc2 = fmaf(w.z, tanh_fast(a.z + c2.z), acc2);
            acc2 = fmaf(w.w, tanh_fast(a.w + c2.w), acc2);
            acc3 = fmaf(w.x, tanh_fast(a.x + c3.x), acc3);
            acc3 = fmaf(w.y, tanh_fast(a.y + c3.y), acc3);
            acc3 = fmaf(w.z, tanh_fast(a.z + c3.z), acc3);
            acc3 = fmaf(w.w, tanh_fast(a.w + c3.w), acc3);
        }
        acc0 += __shfl_xor_sync(0xffffffffu, acc0, 1);
        acc0 += __shfl_xor_sync(0xffffffffu, acc0, 2);
        acc0 += __shfl_xor_sync(0xffffffffu, acc0, 4);
        acc1 += __shfl_xor_sync(0xffffffffu, acc1, 1);
        acc1 += __shfl_xor_sync(0xffffffffu, acc1, 2);
        acc1 += __shfl_xor_sync(0xffffffffu, acc1, 4);
        acc2 += __shfl_xor_sync(0xffffffffu, acc2, 1);
        acc2 += __shfl_xor_sync(0xffffffffu, acc2, 2);
        acc2 += __shfl_xor_sync(0xffffffffu, acc2, 4);
        acc3 += __shfl_xor_sync(0xffffffffu, acc3, 1);
        acc3 += __shfl_xor_sync(0xffffffffu, acc3, 2);
        acc3 += __shfl_xor_sync(0xffffffffu, acc3, 4);
        if (hc < 4) {
            float myacc = (hc == 0) ? acc0 : (hc == 1) ? acc1 : (hc == 2) ? acc2 : acc3;
            int slot = v0 + t * AVT + vg * 4 + hc;
            if (slot < cnt) {
                float p = fast_ex2((myacc + bcv) * 1.4426950408889634f);
                g_sc[(size_t)(b * QQ + q0 + q) * VV + slot] = p;
            }
        }
        __syncthreads();
    }
}

// ---------------------------------------------------------------------------
// K3b: softmax + context over compacted slots. grid 128, 512 threads.
// ---------------------------------------------------------------------------
#define VT 32
#define VP (VV + 8)
#define B_SMEM_FLOATS (8*VP + 16 + 512 + 4096 + 2*VT*HP)
#define B_SMEM_BYTES (B_SMEM_FLOATS*4)

__device__ __forceinline__ void load_tile32_g(float* dst, const float* base,
                                              const int* idx, int tid) {
#pragma unroll
    for (int i = 0; i < 8; i++) {
        int lin = i * 512 + tid;
        int r = lin >> 7;
        int c = (lin & 127) << 2;
        cp_async16(dst + r * HP + c, base + (size_t)idx[r] * HH + c);
    }
}

__global__ __launch_bounds__(512, 1) void ctx_kernel(
    const float* __restrict__ values,
    float* __restrict__ out_ctx, float* __restrict__ out_w) {
    extern __shared__ float smb[];
    float* sc   = smb;                 // 8*VP  (compact weights)
    float* wsum = sc + 8 * VP;         // 16
    int* idxs   = (int*)(wsum + 16);   // 512
    float* xb   = (float*)(idxs + 512);// 4096 (weights scatter / combine)
    float* buf  = xb + 4096;           // 2*VT*HP

    const int tid = threadIdx.x;
    const int b = blockIdx.x >> 4;
    const int qt = blockIdx.x & 15;
    const int q0 = qt * 8;
    const int cnt = g_cnt[b];
    const int nt = (cnt + VT - 1) / VT;

    idxs[tid] = g_idx[b * VV + tid];
    __syncthreads();

    const float* valb = values + (size_t)b * VV * HH;

    load_tile32_g(buf, valb, idxs, tid);
    cp_commit();

    // compact scores, zero-padded beyond cnt
#pragma unroll
    for (int i = 0; i < 8; i++) {
        int lin = i * 512 + tid;
        int r = lin >> 9, j = lin & 511;
        sc[r * VP + j] = (j < cnt) ?
            g_sc[(size_t)(b * QQ + q0 + r) * VV + j] : 0.0f;
    }
    __syncthreads();

    // deterministic row sums
    const int q = tid >> 6;
    const int vl = tid & 63;
    {
        float s = 0.0f;
#pragma unroll
        for (int j = 0; j < 8; j++) s += sc[q * VP + vl + 64 * j];
#pragma unroll
        for (int off = 16; off; off >>= 1) s += __shfl_down_sync(0xffffffffu, s, off);
        if ((tid & 31) == 0) wsum[tid >> 5] = s;
    }
    __syncthreads();
    const float inv = 1.0f / (wsum[2 * q] + wsum[2 * q + 1]);

    // normalize compact weights in smem
    {
#pragma unroll
        for (int j = 0; j < 8; j++) {
            int v = vl + 64 * j;
            sc[q * VP + v] *= inv;
        }
    }
    __syncthreads();

    // weights output: scatter compact -> full rows in smem, then coalesced store
#pragma unroll
    for (int i = 0; i < 8; i++) xb[i * 512 + tid] = 0.0f;
    __syncthreads();
#pragma unroll
    for (int i = 0; i < 8; i++) {
        int lin = i * 512 + tid;
        int r = lin >> 9, j = lin & 511;
        if (j < cnt) xb[r * 512 + idxs[j]] = sc[r * VP + j];
    }
    __syncthreads();
#pragma unroll
    for (int i = 0; i < 8; i++) {
        int lin = i * 512 + tid;
        int r = lin >> 9, j = lin & 511;
        out_w[(size_t)(b * QQ + q0 + r) * VV + j] = xb[lin];
    }
    __syncthreads();

    // context over compact tiles (gathered values rows)
    const int ccol = tid & 127;
    const int cqg  = (tid >> 7) & 1;
    const int cvh  = tid >> 8;
    float4 ca0 = make_float4(0.f,0.f,0.f,0.f);
    float4 ca1 = make_float4(0.f,0.f,0.f,0.f);
    float4 ca2 = make_float4(0.f,0.f,0.f,0.f);
    float4 ca3 = make_float4(0.f,0.f,0.f,0.f);

    for (int t = 0; t < nt; t++) {
        float* cur = buf + (t & 1) * VT * HP;
        if (t + 1 < nt) {
            load_tile32_g(buf + ((t + 1) & 1) * VT * HP, valb, idxs + (t + 1) * VT, tid);
            cp_commit();
            cp_wait1();
        } else {
            cp_wait0();
        }
        __syncthreads();

        const float* wq0 = sc + (cqg * 4 + 0) * VP + t * VT + cvh * 16;
        const float* wq1 = sc + (cqg * 4 + 1) * VP + t * VT + cvh * 16;
        const float* wq2 = sc + (cqg * 4 + 2) * VP + t * VT + cvh * 16;
        const float* wq3 = sc + (cqg * 4 + 3) * VP + t * VT + cvh * 16;
        const float* cb = cur + cvh * 16 * HP;
#pragma unroll
        for (int v = 0; v < 16; v++) {
            float4 c = ((const float4*)(cb + v * HP))[ccol];
            float w0 = wq0[v], w1 = wq1[v], w2 = wq2[v], w3 = wq3[v];
            ca0.x = fmaf(w0, c.x, ca0.x); ca0.y = fmaf(w0, c.y, ca0.y);
            ca0.z = fmaf(w0, c.z, ca0.z); ca0.w = fmaf(w0, c.w, ca0.w);
            ca1.x = fmaf(w1, c.x, ca1.x); ca1.y = fmaf(w1, c.y, ca1.y);
            ca1.z = fmaf(w1, c.z, ca1.z); ca1.w = fmaf(w1, c.w, ca1.w);
            ca2.x = fmaf(w2, c.x, ca2.x); ca2.y = fmaf(w2, c.y, ca2.y);
            ca2.z = fmaf(w2, c.z, ca2.z); ca2.w = fmaf(w2, c.w, ca2.w);
            ca3.x = fmaf(w3, c.x, ca3.x); ca3.y = fmaf(w3, c.y, ca3.y);
            ca3.z = fmaf(w3, c.z, ca3.z); ca3.w = fmaf(w3, c.w, ca3.w);
        }
        __syncthreads();
    }

    // combine the two v-halves (deterministic: vh0 + vh1) and write out
    float4* xbv = (float4*)xb;
    const int xi = (cqg * 128 + ccol) * 4;
    if (cvh == 1) {
        xbv[xi + 0] = ca0; xbv[xi + 1] = ca1; xbv[xi + 2] = ca2; xbv[xi + 3] = ca3;
    }
    __syncthreads();
    if (cvh == 0) {
        float4 p0 = xbv[xi + 0], p1 = xbv[xi + 1], p2 = xbv[xi + 2], p3 = xbv[xi + 3];
        ca0.x += p0.x; ca0.y += p0.y; ca0.z += p0.z; ca0.w += p0.w;
        ca1.x += p1.x; ca1.y += p1.y; ca1.z += p1.z; ca1.w += p1.w;
        ca2.x += p2.x; ca2.y += p2.y; ca2.z += p2.z; ca2.w += p2.w;
        ca3.x += p3.x; ca3.y += p3.y; ca3.z += p3.z; ca3.w += p3.w;
        float* oc = out_ctx + (size_t)(b * QQ + q0 + cqg * 4) * HH;
        ((float4*)(oc + 0 * HH))[ccol] = ca0;
        ((float4*)(oc + 1 * HH))[ccol] = ca1;
        ((float4*)(oc + 2 * HH))[ccol] = ca2;
        ((float4*)(oc + 3 * HH))[ccol] = ca3;
    }
}

// ---------------------------------------------------------------------------
// Launch
// ---------------------------------------------------------------------------
extern "C" void kernel_launch(void* const* d_in, const int* in_sizes, int n_in,
                              void* d_out, int out_size) {
    const float* query  = (const float*)d_in[0];
    const float* values = (const float*)d_in[1];
    const int*   mask   = (const int*)d_in[2];
    const float* Wq     = (const float*)d_in[3];
    const float* bq     = (const float*)d_in[4];
    const float* Wv     = (const float*)d_in[5];
    const float* bv     = (const float*)d_in[6];
    const float* wc     = (const float*)d_in[7];
    const float* bc     = (const float*)d_in[8];

    float* out_ctx = (float*)d_out;
    float* out_w   = (float*)d_out + (size_t)BB * QQ * HH;

    void *qp, *vp;
    cudaGetSymbolAddress(&qp, g_qp);
    cudaGetSymbolAddress(&vp, g_vp);

    // K0: mask compaction
    compact_kernel<<<BB, 512>>>(mask);

    // K2: both projections (HMMA floor)
    cudaFuncSetAttribute(gemm_both_kernel, cudaFuncAttributeMaxDynamicSharedMemorySize, GEMM_SMEM_BYTES);
    dim3 gboth(QP_MTILES + VP_MTILES, HH / GBN);
    gemm_both_kernel<<<gboth, 256, GEMM_SMEM_BYTES>>>(query, Wq, bq, values, Wv, bv);

    // K3a: scores over compacted v (early-exit beyond cnt)
    cudaFuncSetAttribute(score_kernel, cudaFuncAttributeMaxDynamicSharedMemorySize, A_SMEM_BYTES);
    score_kernel<<<1024, 256, A_SMEM_BYTES>>>((const float*)qp, (const float*)vp, wc, bc);

    // K3b: softmax + context over compacted slots
    cudaFuncSetAttribute(ctx_kernel, cudaFuncAttributeMaxDynamicSharedMemorySize, B_SMEM_BYTES);
    ctx_kernel<<<128, 512, B_SMEM_BYTES>>>(values, out_ctx, out_w);
}

// round 14
// speedup vs baseline: 1.7105x; 1.1358x over previous
#include <cuda_runtime.h>
#include <cuda_bf16.h>
#include <cstdint>

#define BB 8
#define QQ 128
#define VV 512
#define HH 512

#define NQ (BB*QQ*HH)
#define NV (BB*VV*HH)

// ---------------------------------------------------------------------------
// Device scratch
// ---------------------------------------------------------------------------
__device__ float g_qp[NQ];
__device__ float g_vp[NV];         // COMPACT: per batch, slots [0,cnt) valid
__device__ float g_sc[BB*QQ*VV];   // compact exp-scores
__device__ int   g_idx[BB*VV];     // compacted unmasked v indices (pad 0)
__device__ int   g_cnt[BB];

// ---------------------------------------------------------------------------
// Fast transcendentals
// ---------------------------------------------------------------------------
__device__ __forceinline__ float fast_ex2(float x) {
    float y;
    asm("ex2.approx.ftz.f32 %0, %1;" : "=f"(y) : "f"(x));
    return y;
}
__device__ __forceinline__ float tanh_fast(float x) {
    float y;
    asm("tanh.approx.f32 %0, %1;" : "=f"(y) : "f"(x));
    return y;
}

// cp.async helpers
__device__ __forceinline__ void cp_async16(void* dst_smem, const void* src_gmem) {
    uint32_t d = (uint32_t)__cvta_generic_to_shared(dst_smem);
    asm volatile("cp.async.cg.shared.global [%0], [%1], 16;\n" :: "r"(d), "l"(src_gmem) : "memory");
}
__device__ __forceinline__ void cp_commit() {
    asm volatile("cp.async.commit_group;\n" ::: "memory");
}
__device__ __forceinline__ void cp_wait1() {
    asm volatile("cp.async.wait_group 1;\n" ::: "memory");
}
__device__ __forceinline__ void cp_wait0() {
    asm volatile("cp.async.wait_group 0;\n" ::: "memory");
}

// ldmatrix x4 (b16)
__device__ __forceinline__ void ldsm_x4(uint32_t* r, uint32_t addr) {
    asm volatile("ldmatrix.sync.aligned.m8n8.x4.shared.b16 {%0,%1,%2,%3}, [%4];"
        : "=r"(r[0]), "=r"(r[1]), "=r"(r[2]), "=r"(r[3]) : "r"(addr));
}

// ---------------------------------------------------------------------------
// K0: mask compaction. 8 blocks, 512 threads. Deterministic.
// ---------------------------------------------------------------------------
__global__ void compact_kernel(const int* __restrict__ mask) {
    __shared__ int wsum_s[16];
    __shared__ int wbase_s[16];
    __shared__ int tot_s;
    const int b = blockIdx.x;
    const int tid = threadIdx.x;
    const int m = mask[b * VV + tid];
    unsigned bal = __ballot_sync(0xffffffffu, m != 0);
    int lanep = __popc(bal & ((1u << (tid & 31)) - 1u));
    int wid = tid >> 5;
    if ((tid & 31) == 0) wsum_s[wid] = __popc(bal);
    __syncthreads();
    if (tid == 0) {
        int acc = 0;
        for (int i = 0; i < 16; i++) { wbase_s[i] = acc; acc += wsum_s[i]; }
        tot_s = acc;
        g_cnt[b] = acc;
    }
    __syncthreads();
    if (m) g_idx[b * VV + wbase_s[wid] + lanep] = tid;
    if (tid >= tot_s) g_idx[b * VV + tid] = 0;
}

// ---------------------------------------------------------------------------
// K2: merged projection GEMM. qp tiles dense; vp tiles GATHER unmasked rows
// through g_idx and write COMPACT g_vp (early exit beyond cnt).
// ---------------------------------------------------------------------------
#define GBM 128
#define GBN 64
#define GBK 64
#define GSTRIDE (GBK + 8)
#define QP_MTILES (BB*QQ/GBM)   // 8
#define VP_MTILES (BB*VV/GBM)   // 32

#define GEMM_SMEM_BF16 (2*GBM*GSTRIDE + 2*GBN*GSTRIDE)
#define GEMM_SMEM_BYTES (GEMM_SMEM_BF16 * 2)
#define ALO_B (GBM*GSTRIDE*2)
#define BLO_B (GBN*GSTRIDE*2)

__device__ __forceinline__ void mma16816(float* d, const uint32_t* a, const uint32_t* b) {
    asm volatile(
        "mma.sync.aligned.m16n8k16.row.col.f32.bf16.bf16.f32 "
        "{%0,%1,%2,%3}, {%4,%5,%6,%7}, {%8,%9}, {%0,%1,%2,%3};"
        : "+f"(d[0]), "+f"(d[1]), "+f"(d[2]), "+f"(d[3])
        : "r"(a[0]), "r"(a[1]), "r"(a[2]), "r"(a[3]), "r"(b[0]), "r"(b[1]));
}

__device__ __forceinline__ void split4(float4 v, uint2* hi, uint2* lo) {
    __nv_bfloat16 h0 = __float2bfloat16(v.x);
    __nv_bfloat16 h1 = __float2bfloat16(v.y);
    __nv_bfloat16 h2 = __float2bfloat16(v.z);
    __nv_bfloat16 h3 = __float2bfloat16(v.w);
    __nv_bfloat16 l0 = __float2bfloat16(v.x - __bfloat162float(h0));
    __nv_bfloat16 l1 = __float2bfloat16(v.y - __bfloat162float(h1));
    __nv_bfloat16 l2 = __float2bfloat16(v.z - __bfloat162float(h2));
    __nv_bfloat16 l3 = __float2bfloat16(v.w - __bfloat162float(h3));
    __nv_bfloat162 hA = {h0, h1}, hB = {h2, h3};
    __nv_bfloat162 lA = {l0, l1}, lB = {l2, l3};
    hi->x = *(uint32_t*)&hA; hi->y = *(uint32_t*)&hB;
    lo->x = *(uint32_t*)&lA; lo->y = *(uint32_t*)&lB;
}

__global__ __launch_bounds__(256, 2) void gemm_both_kernel(
    const float* __restrict__ query, const float* __restrict__ Wq,
    const float* __restrict__ bq,
    const float* __restrict__ values, const float* __restrict__ Wv,
    const float* __restrict__ bv) {
    const int K = HH;
    const int N = HH;
    extern __shared__ __nv_bfloat16 gsm[];
    __nv_bfloat16* As = gsm;
    __nv_bfloat16* Bs = gsm + 2 * GBM * GSTRIDE;

    const float *A, *B, *bias;
    float* C;
    int mt = blockIdx.x;
    const int tid = threadIdx.x;
    const int sr = tid >> 4;            // staging row-within-16
    const int scc = (tid & 15) * 4;

    int m0;             // global compact output row base
    int arow[8];        // per-thread gathered A row indices
    if (mt < QP_MTILES) {
        A = query; B = Wq; bias = bq; C = g_qp;
        m0 = mt * GBM;
#pragma unroll
        for (int i = 0; i < 8; i++) arow[i] = m0 + i * 16 + sr;
    } else {
        mt -= QP_MTILES;
        const int b = mt >> 2;
        const int slot0 = (mt & 3) * GBM;
        if (slot0 >= g_cnt[b]) return;          // whole tile beyond cnt
        A = values; B = Wv; bias = bv; C = g_vp;
        m0 = b * VV + slot0;
#pragma unroll
        for (int i = 0; i < 8; i++)
            arow[i] = b * VV + g_idx[b * VV + slot0 + i * 16 + sr];  // pad->row 0
    }
    const int n0 = blockIdx.y * GBN;
    const int wid = tid >> 5;
    const int lane = tid & 31;
    const int wm = (wid >> 1) * 32;
    const int wn = (wid & 1) * 32;
    const int gp = lane >> 2;
    const int tg = lane & 3;

    const uint32_t As_b = (uint32_t)__cvta_generic_to_shared(As);
    const uint32_t Bs_b = (uint32_t)__cvta_generic_to_shared(Bs);
    const uint32_t aoff = ((wm + (lane & 15)) * GSTRIDE + ((lane >> 4) * 8)) * 2;
    const uint32_t boff = ((wn + ((lane >> 4) & 1) * 8 + (lane & 7)) * GSTRIDE
                           + ((lane >> 3) & 1) * 8) * 2;

    float d[2][4][4];
#pragma unroll
    for (int mi = 0; mi < 2; mi++)
#pragma unroll
        for (int ni = 0; ni < 4; ni++)
#pragma unroll
            for (int r = 0; r < 4; r++) d[mi][ni][r] = 0.0f;

    float4 aReg[8], bReg[4];
#pragma unroll
    for (int i = 0; i < 8; i++)
        aReg[i] = *(const float4*)(A + (size_t)arow[i] * K + scc);
#pragma unroll
    for (int i = 0; i < 4; i++)
        bReg[i] = *(const float4*)(B + (size_t)(n0 + i * 16 + sr) * K + scc);

    for (int k0 = 0; k0 < K; k0 += GBK) {
#pragma unroll
        for (int i = 0; i < 8; i++) {
            uint2 hi, lo;
            split4(aReg[i], &hi, &lo);
            int r = i * 16 + sr;
            *(uint2*)(As + r * GSTRIDE + scc) = hi;
            *(uint2*)(As + GBM * GSTRIDE + r * GSTRIDE + scc) = lo;
        }
#pragma unroll
        for (int i = 0; i < 4; i++) {
            uint2 hi, lo;
            split4(bReg[i], &hi, &lo);
            int r = i * 16 + sr;
            *(uint2*)(Bs + r * GSTRIDE + scc) = hi;
            *(uint2*)(Bs + GBN * GSTRIDE + r * GSTRIDE + scc) = lo;
        }
        __syncthreads();

        if (k0 + GBK < K) {
            int kn = k0 + GBK;
#pragma unroll
            for (int i = 0; i < 8; i++)
                aReg[i] = *(const float4*)(A + (size_t)arow[i] * K + kn + scc);
#pragma unroll
            for (int i = 0; i < 4; i++)
                bReg[i] = *(const float4*)(B + (size_t)(n0 + i * 16 + sr) * K + kn + scc);
        }

#pragma unroll
        for (int ks = 0; ks < GBK; ks += 16) {
            const uint32_t kb = ks * 2;
            uint32_t ah[2][4], al[2][4], bh[2][4], bl[2][4];
            ldsm_x4(ah[0], As_b + aoff + kb);
            ldsm_x4(ah[1], As_b + aoff + 16 * GSTRIDE * 2 + kb);
            ldsm_x4(al[0], As_b + ALO_B + aoff + kb);
            ldsm_x4(al[1], As_b + ALO_B + aoff + 16 * GSTRIDE * 2 + kb);
            ldsm_x4(bh[0], Bs_b + boff + kb);
            ldsm_x4(bh[1], Bs_b + boff + 16 * GSTRIDE * 2 + kb);
            ldsm_x4(bl[0], Bs_b + BLO_B + boff + kb);
            ldsm_x4(bl[1], Bs_b + BLO_B + boff + 16 * GSTRIDE * 2 + kb);
#pragma unroll
            for (int mi = 0; mi < 2; mi++)
#pragma unroll
                for (int ni = 0; ni < 4; ni++)
                    mma16816(d[mi][ni], ah[mi], &bh[ni >> 1][(ni & 1) * 2]);
#pragma unroll
            for (int mi = 0; mi < 2; mi++)
#pragma unroll
                for (int ni = 0; ni < 4; ni++)
                    mma16816(d[mi][ni], ah[mi], &bl[ni >> 1][(ni & 1) * 2]);
#pragma unroll
            for (int mi = 0; mi < 2; mi++)
#pragma unroll
                for (int ni = 0; ni < 4; ni++)
                    mma16816(d[mi][ni], al[mi], &bh[ni >> 1][(ni & 1) * 2]);
        }
        __syncthreads();
    }

#pragma unroll
    for (int mi = 0; mi < 2; mi++)
#pragma unroll
        for (int ni = 0; ni < 4; ni++) {
            int r = m0 + wm + mi * 16 + gp;
            int c = n0 + wn + ni * 8 + tg * 2;
            float b0 = bias[c], b1 = bias[c + 1];
            float* Cp = C + (size_t)r * N + c;
            float2 v0 = make_float2(d[mi][ni][0] + b0, d[mi][ni][1] + b1);
            float2 v1 = make_float2(d[mi][ni][2] + b0, d[mi][ni][3] + b1);
            *(float2*)(Cp) = v0;
            *(float2*)(Cp + 8 * N) = v1;
        }
}

// ---------------------------------------------------------------------------
// K3a: score kernel over compact slots; vp now read LINEARLY from compact g_vp.
// 1024 blocks (early-exit), 256 threads, occ 2.
// ---------------------------------------------------------------------------
#define AVT 16
#define ANT 4
#define HP (HH + 4)
#define A_SMEM_FLOATS (8*HP + HH + 2*AVT*HP)
#define A_SMEM_BYTES (A_SMEM_FLOATS*4)

__device__ __forceinline__ void load_tile16(float* dst, const float* src, int tid) {
#pragma unroll
    for (int i = 0; i < 8; i++) {
        int lin = i * 256 + tid;
        int r = lin >> 7;
        int c = (lin & 127) << 2;
        cp_async16(dst + r * HP + c, src + (size_t)r * HH + c);
    }
}

__global__ __launch_bounds__(256, 2) void score_kernel(
    const float* __restrict__ qp, const float* __restrict__ wc,
    const float* __restrict__ bc) {
    extern __shared__ float sma[];
    float* qp_s = sma;                 // 8*HP
    float* wc_s = qp_s + 8 * HP;       // HH
    float* buf = wc_s + HH;            // 2*AVT*HP

    const int tid = threadIdx.x;
    const int bx = blockIdx.x;
    const int vc = bx & 7;
    const int qt = (bx >> 3) & 15;
    const int b = bx >> 7;
    const int q0 = qt * 8;
    const int v0 = vc * 64;

    const int cnt = g_cnt[b];
    if (v0 >= cnt) return;

    const float* vpb = g_vp + (size_t)(b * VV + v0) * HH;   // compact rows

    load_tile16(buf, vpb, tid);
    cp_commit();

#pragma unroll
    for (int i = 0; i < 4; i++) {
        int lin = i * 256 + tid;
        int r = lin >> 7, c = lin & 127;
        ((float4*)(qp_s + r * HP))[c] =
            ((const float4*)(qp + (size_t)(b * QQ + q0 + r) * HH))[c];
    }
    if (tid < 128) ((float4*)wc_s)[tid] = ((const float4*)wc)[tid];
    const float bcv = bc[0];

    const int q = tid >> 5;
    const int lane = tid & 31;
    const int hc = lane & 7;
    const int vg = lane >> 3;

    for (int t = 0; t < ANT; t++) {
        float* cur = buf + (t & 1) * AVT * HP;
        if (t + 1 < ANT) {
            load_tile16(buf + ((t + 1) & 1) * AVT * HP, vpb + (size_t)(t + 1) * AVT * HH, tid);
            cp_commit();
            cp_wait1();
        } else {
            cp_wait0();
        }
        __syncthreads();

        const float* qrow = qp_s + q * HP;
        const float* wrow = wc_s;
        const float* v0p = cur + (vg * 4 + 0) * HP;
        const float* v1p = cur + (vg * 4 + 1) * HP;
        const float* v2p = cur + (vg * 4 + 2) * HP;
        const float* v3p = cur + (vg * 4 + 3) * HP;
        float acc0 = 0.f, acc1 = 0.f, acc2 = 0.f, acc3 = 0.f;
#pragma unroll
        for (int i = 0; i < 16; i++) {
            int h = i * 32 + hc * 4;
            float4 a = *(const float4*)(qrow + h);
            float4 w = *(const float4*)(wrow + h);
            float4 c0 = *(const float4*)(v0p + h);
            float4 c1 = *(const float4*)(v1p + h);
            float4 c2 = *(const float4*)(v2p + h);
            float4 c3 = *(const float4*)(v3p + h);
            acc0 = fmaf(w.x, tanh_fast(a.x + c0.x), acc0);
            acc0 = fmaf(w.y, tanh_fast(a.y + c0.y), acc0);
            acc0 = fmaf(w.z, tanh_fast(a.z + c0.z), acc0);
            acc0 = fmaf(w.w, tanh_fast(a.w + c0.w), acc0);
            acc1 = fmaf(w.x, tanh_fast(a.x + c1.x), acc1);
            acc1 = fmaf(w.y, tanh_fast(a.y + c1.y), acc1);
            acc1 = fmaf(w.z, tanh_fast(a.z + c1.z), acc1);
            acc1 = fmaf(w.w, tanh_fast(a.w + c1.w), acc1);
            acc2 = fmaf(w.x, tanh_fast(a.x + c2.x), acc2);
            acc2 = fmaf(w.y, tanh_fast(a.y + c2.y), acc2);
            acc2 = fmaf(w.z, tanh_fast(a.z + c2.z), acc2);
            acc2 = fmaf(w.w, tanh_fast(a.w + c2.w), acc2);
            acc3 = fmaf(w.x, tanh_fast(a.x + c3.x), acc3);
            acc3 = fmaf(w.y, tanh_fast(a.y + c3.y), acc3);
            acc3 = fmaf(w.z, tanh_fast(a.z + c3.z), acc3);
            acc3 = fmaf(w.w, tanh_fast(a.w + c3.w), acc3);
        }
        acc0 += __shfl_xor_sync(0xffffffffu, acc0, 1);
        acc0 += __shfl_xor_sync(0xffffffffu, acc0, 2);
        acc0 += __shfl_xor_sync(0xffffffffu, acc0, 4);
        acc1 += __shfl_xor_sync(0xffffffffu, acc1, 1);
        acc1 += __shfl_xor_sync(0xffffffffu, acc1, 2);
        acc1 += __shfl_xor_sync(0xffffffffu, acc1, 4);
        acc2 += __shfl_xor_sync(0xffffffffu, acc2, 1);
        acc2 += __shfl_xor_sync(0xffffffffu, acc2, 2);
        acc2 += __shfl_xor_sync(0xffffffffu, acc2, 4);
        acc3 += __shfl_xor_sync(0xffffffffu, acc3, 1);
        acc3 += __shfl_xor_sync(0xffffffffu, acc3, 2);
        acc3 += __shfl_xor_sync(0xffffffffu, acc3, 4);
        if (hc < 4) {
            float myacc = (hc == 0) ? acc0 : (hc == 1) ? acc1 : (hc == 2) ? acc2 : acc3;
            int slot = v0 + t * AVT + vg * 4 + hc;
            if (slot < cnt) {
                float p = fast_ex2((myacc + bcv) * 1.4426950408889634f);
                g_sc[(size_t)(b * QQ + q0 + q) * VV + slot] = p;
            }
        }
        __syncthreads();
    }
}

// ---------------------------------------------------------------------------
// K3b: softmax + context over compacted slots (unchanged from R13).
// ---------------------------------------------------------------------------
#define VT 32
#define VP (VV + 8)
#define B_SMEM_FLOATS (8*VP + 16 + 512 + 4096 + 2*VT*HP)
#define B_SMEM_BYTES (B_SMEM_FLOATS*4)

__device__ __forceinline__ void load_tile32_g(float* dst, const float* base,
                                              const int* idx, int tid) {
#pragma unroll
    for (int i = 0; i < 8; i++) {
        int lin = i * 512 + tid;
        int r = lin >> 7;
        int c = (lin & 127) << 2;
        cp_async16(dst + r * HP + c, base + (size_t)idx[r] * HH + c);
    }
}

__global__ __launch_bounds__(512, 1) void ctx_kernel(
    const float* __restrict__ values,
    float* __restrict__ out_ctx, float* __restrict__ out_w) {
    extern __shared__ float smb[];
    float* sc   = smb;
    float* wsum = sc + 8 * VP;
    int* idxs   = (int*)(wsum + 16);
    float* xb   = (float*)(idxs + 512);
    float* buf  = xb + 4096;

    const int tid = threadIdx.x;
    const int b = blockIdx.x >> 4;
    const int qt = blockIdx.x & 15;
    const int q0 = qt * 8;
    const int cnt = g_cnt[b];
    const int nt = (cnt + VT - 1) / VT;

    idxs[tid] = g_idx[b * VV + tid];
    __syncthreads();

    const float* valb = values + (size_t)b * VV * HH;

    load_tile32_g(buf, valb, idxs, tid);
    cp_commit();

#pragma unroll
    for (int i = 0; i < 8; i++) {
        int lin = i * 512 + tid;
        int r = lin >> 9, j = lin & 511;
        sc[r * VP + j] = (j < cnt) ?
            g_sc[(size_t)(b * QQ + q0 + r) * VV + j] : 0.0f;
    }
    __syncthreads();

    const int q = tid >> 6;
    const int vl = tid & 63;
    {
        float s = 0.0f;
#pragma unroll
        for (int j = 0; j < 8; j++) s += sc[q * VP + vl + 64 * j];
#pragma unroll
        for (int off = 16; off; off >>= 1) s += __shfl_down_sync(0xffffffffu, s, off);
        if ((tid & 31) == 0) wsum[tid >> 5] = s;
    }
    __syncthreads();
    const float inv = 1.0f / (wsum[2 * q] + wsum[2 * q + 1]);

    {
#pragma unroll
        for (int j = 0; j < 8; j++) {
            int v = vl + 64 * j;
            sc[q * VP + v] *= inv;
        }
    }
    __syncthreads();

#pragma unroll
    for (int i = 0; i < 8; i++) xb[i * 512 + tid] = 0.0f;
    __syncthreads();
#pragma unroll
    for (int i = 0; i < 8; i++) {
        int lin = i * 512 + tid;
        int r = lin >> 9, j = lin & 511;
        if (j < cnt) xb[r * 512 + idxs[j]] = sc[r * VP + j];
    }
    __syncthreads();
#pragma unroll
    for (int i = 0; i < 8; i++) {
        int lin = i * 512 + tid;
        int r = lin >> 9, j = lin & 511;
        out_w[(size_t)(b * QQ + q0 + r) * VV + j] = xb[lin];
    }
    __syncthreads();

    const int ccol = tid & 127;
    const int cqg  = (tid >> 7) & 1;
    const int cvh  = tid >> 8;
    float4 ca0 = make_float4(0.f,0.f,0.f,0.f);
    float4 ca1 = make_float4(0.f,0.f,0.f,0.f);
    float4 ca2 = make_float4(0.f,0.f,0.f,0.f);
    float4 ca3 = make_float4(0.f,0.f,0.f,0.f);

    for (int t = 0; t < nt; t++) {
        float* cur = buf + (t & 1) * VT * HP;
        if (t + 1 < nt) {
            load_tile32_g(buf + ((t + 1) & 1) * VT * HP, valb, idxs + (t + 1) * VT, tid);
            cp_commit();
            cp_wait1();
        } else {
            cp_wait0();
        }
        __syncthreads();

        const float* wq0 = sc + (cqg * 4 + 0) * VP + t * VT + cvh * 16;
        const float* wq1 = sc + (cqg * 4 + 1) * VP + t * VT + cvh * 16;
        const float* wq2 = sc + (cqg * 4 + 2) * VP + t * VT + cvh * 16;
        const float* wq3 = sc + (cqg * 4 + 3) * VP + t * VT + cvh * 16;
        const float* cb = cur + cvh * 16 * HP;
#pragma unroll
        for (int v = 0; v < 16; v++) {
            float4 c = ((const float4*)(cb + v * HP))[ccol];
            float w0 = wq0[v], w1 = wq1[v], w2 = wq2[v], w3 = wq3[v];
            ca0.x = fmaf(w0, c.x, ca0.x); ca0.y = fmaf(w0, c.y, ca0.y);
            ca0.z = fmaf(w0, c.z, ca0.z); ca0.w = fmaf(w0, c.w, ca0.w);
            ca1.x = fmaf(w1, c.x, ca1.x); ca1.y = fmaf(w1, c.y, ca1.y);
            ca1.z = fmaf(w1, c.z, ca1.z); ca1.w = fmaf(w1, c.w, ca1.w);
            ca2.x = fmaf(w2, c.x, ca2.x); ca2.y = fmaf(w2, c.y, ca2.y);
            ca2.z = fmaf(w2, c.z, ca2.z); ca2.w = fmaf(w2, c.w, ca2.w);
            ca3.x = fmaf(w3, c.x, ca3.x); ca3.y = fmaf(w3, c.y, ca3.y);
            ca3.z = fmaf(w3, c.z, ca3.z); ca3.w = fmaf(w3, c.w, ca3.w);
        }
        __syncthreads();
    }

    float4* xbv = (float4*)xb;
    const int xi = (cqg * 128 + ccol) * 4;
    if (cvh == 1) {
        xbv[xi + 0] = ca0; xbv[xi + 1] = ca1; xbv[xi + 2] = ca2; xbv[xi + 3] = ca3;
    }
    __syncthreads();
    if (cvh == 0) {
        float4 p0 = xbv[xi + 0], p1 = xbv[xi + 1], p2 = xbv[xi + 2], p3 = xbv[xi + 3];
        ca0.x += p0.x; ca0.y += p0.y; ca0.z += p0.z; ca0.w += p0.w;
        ca1.x += p1.x; ca1.y += p1.y; ca1.z += p1.z; ca1.w += p1.w;
        ca2.x += p2.x; ca2.y += p2.y; ca2.z += p2.z; ca2.w += p2.w;
        ca3.x += p3.x; ca3.y += p3.y; ca3.z += p3.z; ca3.w += p3.w;
        float* oc = out_ctx + (size_t)(b * QQ + q0 + cqg * 4) * HH;
        ((float4*)(oc + 0 * HH))[ccol] = ca0;
        ((float4*)(oc + 1 * HH))[ccol] = ca1;
        ((float4*)(oc + 2 * HH))[ccol] = ca2;
        ((float4*)(oc + 3 * HH))[ccol] = ca3;
    }
}

// ---------------------------------------------------------------------------
// Launch
// ---------------------------------------------------------------------------
extern "C" void kernel_launch(void* const* d_in, const int* in_sizes, int n_in,
                              void* d_out, int out_size) {
    const float* query  = (const float*)d_in[0];
    const float* values = (const float*)d_in[1];
    const int*   mask   = (const int*)d_in[2];
    const float* Wq     = (const float*)d_in[3];
    const float* bq     = (const float*)d_in[4];
    const float* Wv     = (const float*)d_in[5];
    const float* bv     = (const float*)d_in[6];
    const float* wc     = (const float*)d_in[7];
    const float* bc     = (const float*)d_in[8];

    float* out_ctx = (float*)d_out;
    float* out_w   = (float*)d_out + (size_t)BB * QQ * HH;

    void *qp;
    cudaGetSymbolAddress(&qp, g_qp);

    // K0: mask compaction (must precede GEMM: vp gathers via idx)
    compact_kernel<<<BB, 512>>>(mask);

    // K2: projections; vp tiles gather unmasked rows and early-exit beyond cnt
    cudaFuncSetAttribute(gemm_both_kernel, cudaFuncAttributeMaxDynamicSharedMemorySize, GEMM_SMEM_BYTES);
    dim3 gboth(QP_MTILES + VP_MTILES, HH / GBN);
    gemm_both_kernel<<<gboth, 256, GEMM_SMEM_BYTES>>>(query, Wq, bq, values, Wv, bv);

    // K3a: scores over compact slots (linear compact vp reads)
    cudaFuncSetAttribute(score_kernel, cudaFuncAttributeMaxDynamicSharedMemorySize, A_SMEM_BYTES);
    score_kernel<<<1024, 256, A_SMEM_BYTES>>>((const float*)qp, wc, bc);

    // K3b: softmax + context over compacted slots
    cudaFuncSetAttribute(ctx_kernel, cudaFuncAttributeMaxDynamicSharedMemorySize, B_SMEM_BYTES);
    ctx_kernel<<<128, 512, B_SMEM_BYTES>>>(values, out_ctx, out_w);
}